// round 4
// baseline (speedup 1.0000x reference)
#include <cuda_runtime.h>
#include <cuda_bf16.h>
#include <mma.h>
#include <stdint.h>

using namespace nvcuda;

// Problem dims
#define B_     4096
#define IN_    1024
#define ND_    8192
#define OD_    512
#define DPC_   16
#define KWIN_  819

// ---------------- device scratch ----------------
__device__ float g_xhi[(size_t)B_ * IN_];    // 16 MB
__device__ float g_xlo[(size_t)B_ * IN_];    // 16 MB
__device__ float g_whi[(size_t)ND_ * IN_];   // 32 MB
__device__ float g_wlo[(size_t)ND_ * IN_];   // 32 MB
__device__ float g_w1m[(size_t)ND_ * IN_];   // 32 MB exact masked weights (fixup)
__device__ float g_h  [(size_t)B_ * ND_];    // 128 MB (no bias; added in select)
__device__ int   g_mask_mode;

__device__ __forceinline__ float tf32r(float x) {
    uint32_t u;
    asm("cvt.rna.tf32.f32 %0, %1;" : "=r"(u) : "f"(x));
    return __uint_as_float(u);
}
__device__ __forceinline__ uint32_t smem_u32(const void* p) {
    uint32_t a;
    asm("{ .reg .u64 t; cvta.to.shared.u64 t, %1; cvt.u32.u64 %0, t; }" : "=r"(a) : "l"(p));
    return a;
}
__device__ __forceinline__ void cp_async16(uint32_t dst, const void* src) {
    asm volatile("cp.async.cg.shared.global [%0], [%1], 16;" :: "r"(dst), "l"(src));
}
#define CP_COMMIT()  asm volatile("cp.async.commit_group;" ::: "memory")
#define CP_WAIT_1()  asm volatile("cp.async.wait_group 1;" ::: "memory")
#define CP_WAIT_0()  asm volatile("cp.async.wait_group 0;" ::: "memory")

// ========== kernel 0: probe mask dtype (validated R1) ==========
__global__ void probe_mask_kernel(const unsigned int* __restrict__ m) {
    __shared__ int f_bf16, f_f32, f_u8;
    if (threadIdx.x == 0) { f_bf16 = 0; f_f32 = 0; f_u8 = 0; }
    __syncthreads();
    int lb = 0, lf = 0, lu = 0;
    for (int i = threadIdx.x; i < 4096; i += blockDim.x) {
        unsigned w = m[i];
        if (w == 0x00003F80u || w == 0x3F803F80u)   lb = 1;
        else if (w == 0x3F800000u)                  lf = 1;
        else if (w > 1u && (w & 0xFEFEFEFEu) == 0u) lu = 1;
    }
    if (lb) atomicOr(&f_bf16, 1);
    if (lf) atomicOr(&f_f32, 1);
    if (lu) atomicOr(&f_u8, 1);
    __syncthreads();
    if (threadIdx.x == 0)
        g_mask_mode = f_bf16 ? 3 : (f_f32 ? 1 : (f_u8 ? 0 : 2));
}

// ========== kernel 1a: split x into tf32 hi/lo ==========
__global__ void split_x_kernel(const float* __restrict__ x) {
    int i = blockIdx.x * blockDim.x + threadIdx.x;
    if (i >= B_ * IN_ / 4) return;
    float4 v = ((const float4*)x)[i];
    float4 hi, lo;
    hi.x = tf32r(v.x); lo.x = tf32r(v.x - hi.x);
    hi.y = tf32r(v.y); lo.y = tf32r(v.y - hi.y);
    hi.z = tf32r(v.z); lo.z = tf32r(v.z - hi.z);
    hi.w = tf32r(v.w); lo.w = tf32r(v.w - hi.w);
    ((float4*)g_xhi)[i] = hi;
    ((float4*)g_xlo)[i] = lo;
}

// ========== kernel 1b: mask + split w1 (also store exact masked w) ==========
__global__ void split_w_kernel(const float* __restrict__ w1,
                               const void* __restrict__ mask) {
    int i = blockIdx.x * blockDim.x + threadIdx.x;
    if (i >= ND_ * IN_ / 4) return;
    int mode = g_mask_mode;
    float4 w = ((const float4*)w1)[i];
    bool m0, m1, m2, m3;
    if (mode == 0) {
        uchar4 mm = ((const uchar4*)mask)[i];
        m0 = mm.x; m1 = mm.y; m2 = mm.z; m3 = mm.w;
    } else if (mode == 1) {
        float4 mm = ((const float4*)mask)[i];
        m0 = mm.x != 0.f; m1 = mm.y != 0.f; m2 = mm.z != 0.f; m3 = mm.w != 0.f;
    } else if (mode == 2) {
        int4 mm = ((const int4*)mask)[i];
        m0 = mm.x != 0; m1 = mm.y != 0; m2 = mm.z != 0; m3 = mm.w != 0;
    } else {
        const __nv_bfloat16* mp = ((const __nv_bfloat16*)mask) + (size_t)i * 4;
        m0 = __bfloat162float(mp[0]) != 0.f; m1 = __bfloat162float(mp[1]) != 0.f;
        m2 = __bfloat162float(mp[2]) != 0.f; m3 = __bfloat162float(mp[3]) != 0.f;
    }
    w.x = m0 ? w.x : 0.f; w.y = m1 ? w.y : 0.f;
    w.z = m2 ? w.z : 0.f; w.w = m3 ? w.w : 0.f;
    ((float4*)g_w1m)[i] = w;
    float4 hi, lo;
    hi.x = tf32r(w.x); lo.x = tf32r(w.x - hi.x);
    hi.y = tf32r(w.y); lo.y = tf32r(w.y - hi.y);
    hi.z = tf32r(w.z); lo.z = tf32r(w.z - hi.z);
    hi.w = tf32r(w.w); lo.w = tf32r(w.w - hi.w);
    ((float4*)g_whi)[i] = hi;
    ((float4*)g_wlo)[i] = lo;
}

// ========== kernel 2: wmma tf32 3-product GEMM ==========
#define GM_MT   128
#define GM_NT   256
#define GM_KC   32
#define NCHUNK  (IN_ / GM_KC)        // 32
#define LDS_PAD 36
#define ROWB    (LDS_PAD * 4)        // 144 B

#define OFF_AHI 0
#define OFF_ALO (GM_MT * ROWB)
#define OFF_BHI (2 * GM_MT * ROWB)
#define OFF_BLO (2 * GM_MT * ROWB + GM_NT * ROWB)
#define BUF_SZ  (2 * GM_MT * ROWB + 2 * GM_NT * ROWB)   // 110592
#define GEMM_SMEM (2 * BUF_SZ)                          // 221184

__device__ __forceinline__ void stage_chunk(uint32_t sbuf, int tid,
                                            int m0, int n0, int k0) {
    const float* Xhi = g_xhi; const float* Xlo = g_xlo;
    const float* Whi = g_whi; const float* Wlo = g_wlo;
#pragma unroll
    for (int i = 0; i < 4; i++) {
        int v = tid + i * 256;
        int r = v >> 3, f = v & 7;
        uint32_t so = r * ROWB + f * 16;
        size_t g = (size_t)(m0 + r) * IN_ + k0 + f * 4;
        cp_async16(sbuf + OFF_AHI + so, &Xhi[g]);
        cp_async16(sbuf + OFF_ALO + so, &Xlo[g]);
    }
#pragma unroll
    for (int i = 0; i < 8; i++) {
        int v = tid + i * 256;
        int r = v >> 3, f = v & 7;
        uint32_t so = r * ROWB + f * 16;
        size_t g = (size_t)(n0 + r) * IN_ + k0 + f * 4;
        cp_async16(sbuf + OFF_BHI + so, &Whi[g]);
        cp_async16(sbuf + OFF_BLO + so, &Wlo[g]);
    }
}

__global__ void __launch_bounds__(256, 1)
gemm_tf32_kernel() {
    extern __shared__ char smem[];
    uint32_t sbase = smem_u32(smem);
    int tid = threadIdx.x;
    int wid = tid >> 5;
    int wm = wid & 1;
    int wn = wid >> 1;

    int ing   = blockIdx.x & 255;
    int ntile = (blockIdx.x >> 8) * 8 + (ing & 7);
    int mtile = ing >> 3;
    int m0 = mtile * GM_MT;
    int n0 = ntile * GM_NT;

    wmma::fragment<wmma::accumulator, 16, 16, 8, float> acc[4][4];
#pragma unroll
    for (int i = 0; i < 4; i++)
#pragma unroll
        for (int j = 0; j < 4; j++) wmma::fill_fragment(acc[i][j], 0.f);

    stage_chunk(sbase, tid, m0, n0, 0);
    CP_COMMIT();

    for (int it = 0; it < NCHUNK; ++it) {
        if (it + 1 < NCHUNK) {
            stage_chunk(sbase + ((it + 1) & 1) * BUF_SZ, tid, m0, n0, (it + 1) * GM_KC);
            CP_COMMIT();
            CP_WAIT_1();
        } else {
            CP_WAIT_0();
        }
        __syncthreads();

        const float* buf = (const float*)(smem + (it & 1) * BUF_SZ);
        const float* Ah = buf + (OFF_AHI / 4) + (size_t)wm * 64 * LDS_PAD;
        const float* Al = buf + (OFF_ALO / 4) + (size_t)wm * 64 * LDS_PAD;
        const float* Bh = buf + (OFF_BHI / 4) + (size_t)wn * 64 * LDS_PAD;
        const float* Bl = buf + (OFF_BLO / 4) + (size_t)wn * 64 * LDS_PAD;

#pragma unroll
        for (int ks = 0; ks < 4; ks++) {
            wmma::fragment<wmma::matrix_b, 16, 16, 8, wmma::precision::tf32,
                           wmma::col_major> bh[4], bl[4];
#pragma unroll
            for (int nt = 0; nt < 4; nt++) {
                wmma::load_matrix_sync(bh[nt], Bh + nt * 16 * LDS_PAD + ks * 8, LDS_PAD);
                wmma::load_matrix_sync(bl[nt], Bl + nt * 16 * LDS_PAD + ks * 8, LDS_PAD);
            }
#pragma unroll
            for (int mt = 0; mt < 4; mt++) {
                wmma::fragment<wmma::matrix_a, 16, 16, 8, wmma::precision::tf32,
                               wmma::row_major> ah, al;
                wmma::load_matrix_sync(ah, Ah + mt * 16 * LDS_PAD + ks * 8, LDS_PAD);
                wmma::load_matrix_sync(al, Al + mt * 16 * LDS_PAD + ks * 8, LDS_PAD);
#pragma unroll
                for (int nt = 0; nt < 4; nt++) {
                    wmma::mma_sync(acc[mt][nt], ah, bh[nt], acc[mt][nt]);
                    wmma::mma_sync(acc[mt][nt], ah, bl[nt], acc[mt][nt]);
                    wmma::mma_sync(acc[mt][nt], al, bh[nt], acc[mt][nt]);
                }
            }
        }
        __syncthreads();
    }

    float* base = g_h + (size_t)(m0 + wm * 64) * ND_ + n0 + wn * 64;
#pragma unroll
    for (int mt = 0; mt < 4; mt++)
#pragma unroll
        for (int nt = 0; nt < 4; nt++)
            wmma::store_matrix_sync(base + (size_t)mt * 16 * ND_ + nt * 16,
                                    acc[mt][nt], ND_, wmma::mem_row_major);
}

// ========== kernel 3: top-k + exact borderline fixup + output ==========
__device__ __forceinline__ unsigned fkey(float f) {
    unsigned u = __float_as_uint(f);
    return (u & 0x80000000u) ? ~u : (u | 0x80000000u);
}
__device__ __forceinline__ float key2f(unsigned k) {
    unsigned u = (k & 0x80000000u) ? (k & 0x7FFFFFFFu) : ~k;
    return __uint_as_float(u);
}

#define BAND   2e-5f
#define SMAXN  64

__global__ void __launch_bounds__(512)
select_output_kernel(const float* __restrict__ H,
                     const float* __restrict__ x,
                     const float* __restrict__ b1,
                     const float* __restrict__ w2,
                     const float* __restrict__ b2,
                     float* __restrict__ out) {
    __shared__ unsigned int hist[256];
    __shared__ unsigned int s_prefix;
    __shared__ int s_kk;
    __shared__ int sN, sK1;
    __shared__ int   S_idx[SMAXN];
    __shared__ float S_val[SMAXN];
    __shared__ unsigned char S_win[SMAXN];

    int b = blockIdx.x;
    int t = threadIdx.x;
    int wid = t >> 5, lane = t & 31;

    // thread t owns h[b][t*16 .. t*16+15] == dendrites of output o=t
    const float4* hp = (const float4*)(H + (size_t)b * ND_) + t * 4;
    const float4* bp = (const float4*)(b1) + t * 4;
    float v[16], w[16];
    *(float4*)&v[0]  = hp[0];  *(float4*)&w[0]  = __ldg(bp + 0);
    *(float4*)&v[4]  = hp[1];  *(float4*)&w[4]  = __ldg(bp + 1);
    *(float4*)&v[8]  = hp[2];  *(float4*)&w[8]  = __ldg(bp + 2);
    *(float4*)&v[12] = hp[3];  *(float4*)&w[12] = __ldg(bp + 3);
    unsigned key[16];
#pragma unroll
    for (int j = 0; j < 16; j++) { v[j] += w[j]; key[j] = fkey(v[j]); }

    unsigned prefix = 0;
    int kk = KWIN_;
#pragma unroll 1
    for (int pass = 0; pass < 4; pass++) {
        int shift = 24 - pass * 8;
        if (t < 256) hist[t] = 0;
        __syncthreads();
        if (pass == 0) {
#pragma unroll
            for (int j = 0; j < 16; j++) atomicAdd(&hist[key[j] >> 24], 1u);
        } else {
            unsigned want = prefix >> (shift + 8);
#pragma unroll
            for (int j = 0; j < 16; j++)
                if ((key[j] >> (shift + 8)) == want)
                    atomicAdd(&hist[(key[j] >> shift) & 255u], 1u);
        }
        __syncthreads();
        if (t == 0) {
            unsigned cum = 0; int bin = 255;
            for (; bin > 0; bin--) {
                unsigned c = hist[bin];
                if (cum + c >= (unsigned)kk) break;
                cum += c;
            }
            s_prefix = prefix | ((unsigned)bin << shift);
            s_kk = kk - (int)cum;
        }
        __syncthreads();
        prefix = s_prefix;
        kk = s_kk;
        __syncthreads();
    }
    float thr_f = key2f(prefix);

    // ---- borderline fixup ----
    if (t == 0) { sN = 0; sK1 = 0; }
    __syncthreads();
    signed char sloc[16];
    int cert = 0;
#pragma unroll
    for (int j = 0; j < 16; j++) {
        sloc[j] = -1;
        if (v[j] > thr_f + BAND) cert++;
        else if (v[j] >= thr_f - BAND) {
            int s = atomicAdd(&sN, 1);
            if (s < SMAXN) { S_idx[s] = t * DPC_ + j; sloc[j] = (signed char)s; }
        }
    }
    if (cert) atomicAdd(&sK1, cert);
    __syncthreads();
    int nS = sN < SMAXN ? sN : SMAXN;

    // exact fp32 recompute of borderline elements (one warp each)
    for (int s = wid; s < nS; s += 16) {
        int j = S_idx[s];
        const float* xr = x + (size_t)b * IN_;
        const float* wr = g_w1m + (size_t)j * IN_;
        int k0 = lane * 32;
        float a = 0.f;
#pragma unroll
        for (int q = 0; q < 8; q++) {
            float4 xv = __ldg((const float4*)(xr + k0 + q * 4));
            float4 wv = __ldg((const float4*)(wr + k0 + q * 4));
            a = fmaf(xv.x, wv.x, a); a = fmaf(xv.y, wv.y, a);
            a = fmaf(xv.z, wv.z, a); a = fmaf(xv.w, wv.w, a);
        }
#pragma unroll
        for (int off = 16; off; off >>= 1) a += __shfl_down_sync(0xFFFFFFFFu, a, off);
        if (lane == 0) S_val[s] = a + __ldg(&b1[j]);
    }
    __syncthreads();
    if (t == 0) {
        int need = KWIN_ - sK1;
        for (int s = 0; s < nS; s++) S_win[s] = 0;
        for (int r = 0; r < need && r < nS; r++) {
            int best = -1;
            for (int s = 0; s < nS; s++) {
                if (S_win[s]) continue;
                if (best < 0 || S_val[s] > S_val[best] ||
                    (S_val[s] == S_val[best] && S_idx[s] < S_idx[best])) best = s;
            }
            if (best >= 0) S_win[best] = 1;
        }
    }
    __syncthreads();

    // ---- block-diagonal contraction ----
    const float* w2p = w2 + (size_t)t * (DPC_ * OD_) + t * DPC_;
    *(float4*)&w[0]  = __ldg((const float4*)(w2p + 0));
    *(float4*)&w[4]  = __ldg((const float4*)(w2p + 4));
    *(float4*)&w[8]  = __ldg((const float4*)(w2p + 8));
    *(float4*)&w[12] = __ldg((const float4*)(w2p + 12));
    float s_out = __ldg(&b2[t]);
#pragma unroll
    for (int j = 0; j < 16; j++) {
        bool win; float val = v[j];
        if (v[j] > thr_f + BAND) win = true;
        else if (sloc[j] >= 0) { win = (S_win[sloc[j]] != 0); val = S_val[sloc[j]]; }
        else win = (v[j] >= thr_f - BAND) ? (key[j] >= prefix) : false;  // overflow fallback
        if (win) s_out += val * w[j];
    }
    out[(size_t)b * OD_ + t] = s_out;
}

// ========== launcher ==========
extern "C" void kernel_launch(void* const* d_in, const int* in_sizes, int n_in,
                              void* d_out, int out_size) {
    const float* x   = (const float*)d_in[0];
    const float* w1  = (const float*)d_in[1];
    const float* b1  = (const float*)d_in[2];
    const void*  msk = d_in[3];
    const float* w2  = (const float*)d_in[4];
    const float* b2  = (const float*)d_in[5];
    float* out = (float*)d_out;

    float* h_ptr; cudaGetSymbolAddress((void**)&h_ptr, g_h);

    cudaFuncSetAttribute(gemm_tf32_kernel,
                         cudaFuncAttributeMaxDynamicSharedMemorySize, GEMM_SMEM);

    probe_mask_kernel<<<1, 256>>>((const unsigned int*)msk);
    split_x_kernel<<<(B_ * IN_ / 4 + 255) / 256, 256>>>(x);
    split_w_kernel<<<(ND_ * IN_ / 4 + 255) / 256, 256>>>(w1, msk);
    gemm_tf32_kernel<<<(B_ / GM_MT) * (ND_ / GM_NT), 256, GEMM_SMEM>>>();
    select_output_kernel<<<B_, 512>>>(h_ptr, x, b1, w2, b2, out);
}

// round 7
// speedup vs baseline: 1.3280x; 1.3280x over previous
#include <cuda_runtime.h>
#include <cuda_bf16.h>
#include <cuda_fp16.h>
#include <mma.h>
#include <stdint.h>

using namespace nvcuda;

// Problem dims
#define B_     4096
#define IN_    1024
#define ND_    8192
#define OD_    512
#define DPC_   16
#define KWIN_  819

// ---------------- device scratch ----------------
__device__ __align__(16) __half g_xhi[(size_t)B_ * IN_];    // 8 MB
__device__ __align__(16) __half g_xlo[(size_t)B_ * IN_];    // 8 MB
__device__ __align__(16) __half g_whi[(size_t)ND_ * IN_];   // 16 MB
__device__ __align__(16) __half g_wlo[(size_t)ND_ * IN_];   // 16 MB
__device__ __align__(16) float  g_w1m[(size_t)ND_ * IN_];   // 32 MB exact masked weights
__device__ __align__(16) float  g_h  [(size_t)B_ * ND_];    // 128 MB (no bias)
__device__ int   g_mask_mode;

__device__ __forceinline__ uint32_t smem_u32(const void* p) {
    uint32_t a;
    asm("{ .reg .u64 t; cvta.to.shared.u64 t, %1; cvt.u32.u64 %0, t; }" : "=r"(a) : "l"(p));
    return a;
}
__device__ __forceinline__ void cp_async16(uint32_t dst, const void* src) {
    asm volatile("cp.async.cg.shared.global [%0], [%1], 16;" :: "r"(dst), "l"(src));
}
#define CP_COMMIT()  asm volatile("cp.async.commit_group;" ::: "memory")
#define CP_WAIT_1()  asm volatile("cp.async.wait_group 1;" ::: "memory")
#define CP_WAIT_0()  asm volatile("cp.async.wait_group 0;" ::: "memory")

// ========== kernel 0: probe mask dtype (validated R1) ==========
__global__ void probe_mask_kernel(const unsigned int* __restrict__ m) {
    __shared__ int f_bf16, f_f32, f_u8;
    if (threadIdx.x == 0) { f_bf16 = 0; f_f32 = 0; f_u8 = 0; }
    __syncthreads();
    int lb = 0, lf = 0, lu = 0;
    for (int i = threadIdx.x; i < 4096; i += blockDim.x) {
        unsigned w = m[i];
        if (w == 0x00003F80u || w == 0x3F803F80u)   lb = 1;
        else if (w == 0x3F800000u)                  lf = 1;
        else if (w > 1u && (w & 0xFEFEFEFEu) == 0u) lu = 1;
    }
    if (lb) atomicOr(&f_bf16, 1);
    if (lf) atomicOr(&f_f32, 1);
    if (lu) atomicOr(&f_u8, 1);
    __syncthreads();
    if (threadIdx.x == 0)
        g_mask_mode = f_bf16 ? 3 : (f_f32 ? 1 : (f_u8 ? 0 : 2));
}

// ========== kernel 1a: split x into fp16 hi/lo ==========
__global__ void split_x_kernel(const float* __restrict__ x) {
    int i = blockIdx.x * blockDim.x + threadIdx.x;
    if (i >= B_ * IN_ / 4) return;
    float4 v = ((const float4*)x)[i];
    __half h[4], l[4];
    h[0] = __float2half_rn(v.x); l[0] = __float2half_rn(v.x - __half2float(h[0]));
    h[1] = __float2half_rn(v.y); l[1] = __float2half_rn(v.y - __half2float(h[1]));
    h[2] = __float2half_rn(v.z); l[2] = __float2half_rn(v.z - __half2float(h[2]));
    h[3] = __float2half_rn(v.w); l[3] = __float2half_rn(v.w - __half2float(h[3]));
    ((uint2*)g_xhi)[i] = *(uint2*)h;
    ((uint2*)g_xlo)[i] = *(uint2*)l;
}

// ========== kernel 1b: mask + split w1 (also store exact masked w) ==========
__global__ void split_w_kernel(const float* __restrict__ w1,
                               const void* __restrict__ mask) {
    int i = blockIdx.x * blockDim.x + threadIdx.x;
    if (i >= ND_ * IN_ / 4) return;
    int mode = g_mask_mode;
    float4 w = ((const float4*)w1)[i];
    bool m0, m1, m2, m3;
    if (mode == 0) {
        uchar4 mm = ((const uchar4*)mask)[i];
        m0 = mm.x; m1 = mm.y; m2 = mm.z; m3 = mm.w;
    } else if (mode == 1) {
        float4 mm = ((const float4*)mask)[i];
        m0 = mm.x != 0.f; m1 = mm.y != 0.f; m2 = mm.z != 0.f; m3 = mm.w != 0.f;
    } else if (mode == 2) {
        int4 mm = ((const int4*)mask)[i];
        m0 = mm.x != 0; m1 = mm.y != 0; m2 = mm.z != 0; m3 = mm.w != 0;
    } else {
        const __nv_bfloat16* mp = ((const __nv_bfloat16*)mask) + (size_t)i * 4;
        m0 = __bfloat162float(mp[0]) != 0.f; m1 = __bfloat162float(mp[1]) != 0.f;
        m2 = __bfloat162float(mp[2]) != 0.f; m3 = __bfloat162float(mp[3]) != 0.f;
    }
    w.x = m0 ? w.x : 0.f; w.y = m1 ? w.y : 0.f;
    w.z = m2 ? w.z : 0.f; w.w = m3 ? w.w : 0.f;
    ((float4*)g_w1m)[i] = w;
    __half h[4], l[4];
    h[0] = __float2half_rn(w.x); l[0] = __float2half_rn(w.x - __half2float(h[0]));
    h[1] = __float2half_rn(w.y); l[1] = __float2half_rn(w.y - __half2float(h[1]));
    h[2] = __float2half_rn(w.z); l[2] = __float2half_rn(w.z - __half2float(h[2]));
    h[3] = __float2half_rn(w.w); l[3] = __float2half_rn(w.w - __half2float(h[3]));
    ((uint2*)g_whi)[i] = *(uint2*)h;
    ((uint2*)g_wlo)[i] = *(uint2*)l;
}

// ========== kernel 2: wmma fp16 3-product GEMM ==========
// h[4096 x 8192] = x @ w^T  (bias deferred to select kernel)
// CTA 128x256, K-chunk 32, 8 warps, warp tile 64x64 (16x16x16 frags).
#define GM_MT   128
#define GM_NT   256
#define GM_KC   32
#define NCHUNK  (IN_ / GM_KC)        // 32
#define ROWH    40                   // halfs per row (32 data + 8 pad), ldm mult of 8
#define ROWB    (ROWH * 2)           // 80 B

#define OFF_AHI 0
#define OFF_ALO (GM_MT * ROWB)                   // 10240
#define OFF_BHI (2 * GM_MT * ROWB)               // 20480
#define OFF_BLO (2 * GM_MT * ROWB + GM_NT * ROWB)// 40960
#define BUF_SZ  (2 * GM_MT * ROWB + 2 * GM_NT * ROWB)  // 61440
#define GEMM_SMEM (2 * BUF_SZ)                         // 122880

__device__ __forceinline__ void stage_chunk(uint32_t sbuf, int tid,
                                            int m0, int n0, int k0) {
    const __half* Xhi = g_xhi; const __half* Xlo = g_xlo;
    const __half* Whi = g_whi; const __half* Wlo = g_wlo;
    // A: 128 rows x 4 x 16B  (512 slots)
#pragma unroll
    for (int i = 0; i < 2; i++) {
        int v = tid + i * 256;
        int r = v >> 2, f = v & 3;
        uint32_t so = r * ROWB + f * 16;
        size_t g = (size_t)(m0 + r) * IN_ + k0 + f * 8;
        cp_async16(sbuf + OFF_AHI + so, &Xhi[g]);
        cp_async16(sbuf + OFF_ALO + so, &Xlo[g]);
    }
    // B: 256 rows x 4 x 16B  (1024 slots)
#pragma unroll
    for (int i = 0; i < 4; i++) {
        int v = tid + i * 256;
        int r = v >> 2, f = v & 3;
        uint32_t so = r * ROWB + f * 16;
        size_t g = (size_t)(n0 + r) * IN_ + k0 + f * 8;
        cp_async16(sbuf + OFF_BHI + so, &Whi[g]);
        cp_async16(sbuf + OFF_BLO + so, &Wlo[g]);
    }
}

__global__ void __launch_bounds__(256, 1)
gemm_fp16_kernel() {
    extern __shared__ char smem[];
    uint32_t sbase = smem_u32(smem);
    int tid = threadIdx.x;
    int wid = tid >> 5;
    int wm = wid & 1;
    int wn = wid >> 1;

    // swizzle: groups of 8 ntiles x 32 mtiles -> B panel + all A in L2
    int ing   = blockIdx.x & 255;
    int ntile = (blockIdx.x >> 8) * 8 + (ing & 7);
    int mtile = ing >> 3;
    int m0 = mtile * GM_MT;
    int n0 = ntile * GM_NT;

    wmma::fragment<wmma::accumulator, 16, 16, 16, float> acc[4][4];
#pragma unroll
    for (int i = 0; i < 4; i++)
#pragma unroll
        for (int j = 0; j < 4; j++) wmma::fill_fragment(acc[i][j], 0.f);

    stage_chunk(sbase, tid, m0, n0, 0);
    CP_COMMIT();

    for (int it = 0; it < NCHUNK; ++it) {
        if (it + 1 < NCHUNK) {
            stage_chunk(sbase + ((it + 1) & 1) * BUF_SZ, tid, m0, n0, (it + 1) * GM_KC);
            CP_COMMIT();
            CP_WAIT_1();
        } else {
            CP_WAIT_0();
        }
        __syncthreads();

        const __half* buf = (const __half*)(smem + (it & 1) * BUF_SZ);
        const __half* Ah = buf + (OFF_AHI / 2) + wm * 64 * ROWH;
        const __half* Al = buf + (OFF_ALO / 2) + wm * 64 * ROWH;
        const __half* Bh = buf + (OFF_BHI / 2) + wn * 64 * ROWH;
        const __half* Bl = buf + (OFF_BLO / 2) + wn * 64 * ROWH;

#pragma unroll
        for (int ks = 0; ks < 2; ks++) {
            wmma::fragment<wmma::matrix_a, 16, 16, 16, __half, wmma::row_major> ah[4], al[4];
#pragma unroll
            for (int mt = 0; mt < 4; mt++) {
                wmma::load_matrix_sync(ah[mt], Ah + mt * 16 * ROWH + ks * 16, ROWH);
                wmma::load_matrix_sync(al[mt], Al + mt * 16 * ROWH + ks * 16, ROWH);
            }
#pragma unroll
            for (int nt = 0; nt < 4; nt++) {
                wmma::fragment<wmma::matrix_b, 16, 16, 16, __half, wmma::col_major> bh, bl;
                wmma::load_matrix_sync(bh, Bh + nt * 16 * ROWH + ks * 16, ROWH);
                wmma::load_matrix_sync(bl, Bl + nt * 16 * ROWH + ks * 16, ROWH);
#pragma unroll
                for (int mt = 0; mt < 4; mt++) {
                    wmma::mma_sync(acc[mt][nt], ah[mt], bh, acc[mt][nt]);
                    wmma::mma_sync(acc[mt][nt], ah[mt], bl, acc[mt][nt]);
                    wmma::mma_sync(acc[mt][nt], al[mt], bh, acc[mt][nt]);
                }
            }
        }
        __syncthreads();
    }

    float* base = g_h + (size_t)(m0 + wm * 64) * ND_ + n0 + wn * 64;
#pragma unroll
    for (int mt = 0; mt < 4; mt++)
#pragma unroll
        for (int nt = 0; nt < 4; nt++)
            wmma::store_matrix_sync(base + (size_t)mt * 16 * ND_ + nt * 16,
                                    acc[mt][nt], ND_, wmma::mem_row_major);
}

// ========== kernel 3: top-k + exact borderline fixup + output ==========
__device__ __forceinline__ unsigned fkey(float f) {
    unsigned u = __float_as_uint(f);
    return (u & 0x80000000u) ? ~u : (u | 0x80000000u);
}
__device__ __forceinline__ float key2f(unsigned k) {
    unsigned u = (k & 0x80000000u) ? (k & 0x7FFFFFFFu) : ~k;
    return __uint_as_float(u);
}

#define BAND   2e-5f
#define SMAXN  64

__global__ void __launch_bounds__(512)
select_output_kernel(const float* __restrict__ H,
                     const float* __restrict__ x,
                     const float* __restrict__ b1,
                     const float* __restrict__ w2,
                     const float* __restrict__ b2,
                     float* __restrict__ out) {
    __shared__ unsigned int hist[256];
    __shared__ unsigned int s_prefix;
    __shared__ int s_kk;
    __shared__ int sN, sK1;
    __shared__ int   S_idx[SMAXN];
    __shared__ float S_val[SMAXN];
    __shared__ unsigned char S_win[SMAXN];

    int b = blockIdx.x;
    int t = threadIdx.x;

    // thread t owns h[b][t*16 .. t*16+15] == dendrites of output o=t
    const float4* hp = (const float4*)(H + (size_t)b * ND_) + t * 4;
    const float4* bp = (const float4*)(b1) + t * 4;
    float v[16], w[16];
    *(float4*)&v[0]  = hp[0];  *(float4*)&w[0]  = __ldg(bp + 0);
    *(float4*)&v[4]  = hp[1];  *(float4*)&w[4]  = __ldg(bp + 1);
    *(float4*)&v[8]  = hp[2];  *(float4*)&w[8]  = __ldg(bp + 2);
    *(float4*)&v[12] = hp[3];  *(float4*)&w[12] = __ldg(bp + 3);
    unsigned key[16];
#pragma unroll
    for (int j = 0; j < 16; j++) { v[j] += w[j]; key[j] = fkey(v[j]); }

    unsigned prefix = 0;
    int kk = KWIN_;
#pragma unroll 1
    for (int pass = 0; pass < 4; pass++) {
        int shift = 24 - pass * 8;
        if (t < 256) hist[t] = 0;
        __syncthreads();
        if (pass == 0) {
#pragma unroll
            for (int j = 0; j < 16; j++) atomicAdd(&hist[key[j] >> 24], 1u);
        } else {
            unsigned want = prefix >> (shift + 8);
#pragma unroll
            for (int j = 0; j < 16; j++)
                if ((key[j] >> (shift + 8)) == want)
                    atomicAdd(&hist[(key[j] >> shift) & 255u], 1u);
        }
        __syncthreads();
        if (t == 0) {
            unsigned cum = 0; int bin = 255;
            for (; bin > 0; bin--) {
                unsigned c = hist[bin];
                if (cum + c >= (unsigned)kk) break;
                cum += c;
            }
            s_prefix = prefix | ((unsigned)bin << shift);
            s_kk = kk - (int)cum;
        }
        __syncthreads();
        prefix = s_prefix;
        kk = s_kk;
        __syncthreads();
    }
    float thr_f = key2f(prefix);

    // ---- borderline detection ----
    if (t == 0) { sN = 0; sK1 = 0; }
    __syncthreads();
    signed char sloc[16];
    int cert = 0;
#pragma unroll
    for (int j = 0; j < 16; j++) {
        sloc[j] = -1;
        if (v[j] > thr_f + BAND) cert++;
        else if (v[j] >= thr_f - BAND) {
            int s = atomicAdd(&sN, 1);
            if (s < SMAXN) { S_idx[s] = t * DPC_ + j; sloc[j] = (signed char)s; }
        }
    }
    if (cert) atomicAdd(&sK1, cert);
    __syncthreads();
    int nS = sN < SMAXN ? sN : SMAXN;

    // exact fp32 recompute, ONE THREAD per element, strictly ascending-k
    // sequential FMA chain (the summation order that matched jax in R1).
    for (int s = t; s < nS; s += 512) {
        int j = S_idx[s];
        const float4* xr = (const float4*)(x + (size_t)b * IN_);
        const float4* wr = (const float4*)(g_w1m + (size_t)j * IN_);
        float a = 0.f;
#pragma unroll 8
        for (int q = 0; q < IN_ / 4; q++) {
            float4 xv = __ldg(xr + q);
            float4 wv = __ldg(wr + q);
            a = fmaf(xv.x, wv.x, a);
            a = fmaf(xv.y, wv.y, a);
            a = fmaf(xv.z, wv.z, a);
            a = fmaf(xv.w, wv.w, a);
        }
        S_val[s] = a + __ldg(&b1[j]);
    }
    __syncthreads();
    if (t == 0) {
        int need = KWIN_ - sK1;
        for (int s = 0; s < nS; s++) S_win[s] = 0;
        for (int r = 0; r < need && r < nS; r++) {
            int best = -1;
            for (int s = 0; s < nS; s++) {
                if (S_win[s]) continue;
                if (best < 0 || S_val[s] > S_val[best] ||
                    (S_val[s] == S_val[best] && S_idx[s] < S_idx[best])) best = s;
            }
            if (best >= 0) S_win[best] = 1;
        }
    }
    __syncthreads();

    // ---- block-diagonal contraction ----
    const float* w2p = w2 + (size_t)t * (DPC_ * OD_) + t * DPC_;
    *(float4*)&w[0]  = __ldg((const float4*)(w2p + 0));
    *(float4*)&w[4]  = __ldg((const float4*)(w2p + 4));
    *(float4*)&w[8]  = __ldg((const float4*)(w2p + 8));
    *(float4*)&w[12] = __ldg((const float4*)(w2p + 12));
    float s_out = __ldg(&b2[t]);
#pragma unroll
    for (int j = 0; j < 16; j++) {
        bool win; float val = v[j];
        if (v[j] > thr_f + BAND) win = true;
        else if (sloc[j] >= 0) { win = (S_win[sloc[j]] != 0); val = S_val[sloc[j]]; }
        else win = (v[j] >= thr_f - BAND) ? (key[j] >= prefix) : false;  // overflow fallback
        if (win) s_out += val * w[j];
    }
    out[(size_t)b * OD_ + t] = s_out;
}

// ========== launcher ==========
extern "C" void kernel_launch(void* const* d_in, const int* in_sizes, int n_in,
                              void* d_out, int out_size) {
    const float* x   = (const float*)d_in[0];
    const float* w1  = (const float*)d_in[1];
    const float* b1  = (const float*)d_in[2];
    const void*  msk = d_in[3];
    const float* w2  = (const float*)d_in[4];
    const float* b2  = (const float*)d_in[5];
    float* out = (float*)d_out;

    float* h_ptr; cudaGetSymbolAddress((void**)&h_ptr, g_h);

    cudaFuncSetAttribute(gemm_fp16_kernel,
                         cudaFuncAttributeMaxDynamicSharedMemorySize, GEMM_SMEM);

    probe_mask_kernel<<<1, 256>>>((const unsigned int*)msk);
    split_x_kernel<<<(B_ * IN_ / 4 + 255) / 256, 256>>>(x);
    split_w_kernel<<<(ND_ * IN_ / 4 + 255) / 256, 256>>>(w1, msk);
    gemm_fp16_kernel<<<(B_ / GM_MT) * (ND_ / GM_NT), 256, GEMM_SMEM>>>();
    select_output_kernel<<<B_, 512>>>(h_ptr, x, b1, w2, b2, out);
}

// round 9
// speedup vs baseline: 2.0053x; 1.5100x over previous
#include <cuda_runtime.h>
#include <cuda_bf16.h>
#include <cuda_fp16.h>
#include <mma.h>
#include <stdint.h>

using namespace nvcuda;

// Problem dims
#define B_     4096
#define IN_    1024
#define ND_    8192
#define OD_    512
#define DPC_   16
#define KWIN_  819

// ---------------- device scratch ----------------
__device__ __align__(16) __half g_xhi[(size_t)B_ * IN_];    // 8 MB
__device__ __align__(16) __half g_xlo[(size_t)B_ * IN_];    // 8 MB
__device__ __align__(16) __half g_whi[(size_t)ND_ * IN_];   // 16 MB
__device__ __align__(16) __half g_wlo[(size_t)ND_ * IN_];   // 16 MB
__device__ __align__(16) float  g_w1m[(size_t)ND_ * IN_];   // 32 MB exact masked weights
__device__ __align__(16) float  g_h  [(size_t)B_ * ND_];    // 128 MB (no bias)
__device__ int   g_mask_mode;

__device__ __forceinline__ uint32_t smem_u32(const void* p) {
    uint32_t a;
    asm("{ .reg .u64 t; cvta.to.shared.u64 t, %1; cvt.u32.u64 %0, t; }" : "=r"(a) : "l"(p));
    return a;
}
__device__ __forceinline__ void cp_async16(uint32_t dst, const void* src) {
    asm volatile("cp.async.cg.shared.global [%0], [%1], 16;" :: "r"(dst), "l"(src));
}
#define CP_COMMIT()  asm volatile("cp.async.commit_group;" ::: "memory")
#define CP_WAIT_2()  asm volatile("cp.async.wait_group 2;" ::: "memory")
#define CP_WAIT_1()  asm volatile("cp.async.wait_group 1;" ::: "memory")
#define CP_WAIT_0()  asm volatile("cp.async.wait_group 0;" ::: "memory")

// ========== kernel 0: probe mask dtype (validated R1) ==========
__global__ void probe_mask_kernel(const unsigned int* __restrict__ m) {
    __shared__ int f_bf16, f_f32, f_u8;
    if (threadIdx.x == 0) { f_bf16 = 0; f_f32 = 0; f_u8 = 0; }
    __syncthreads();
    int lb = 0, lf = 0, lu = 0;
    for (int i = threadIdx.x; i < 4096; i += blockDim.x) {
        unsigned w = m[i];
        if (w == 0x00003F80u || w == 0x3F803F80u)   lb = 1;
        else if (w == 0x3F800000u)                  lf = 1;
        else if (w > 1u && (w & 0xFEFEFEFEu) == 0u) lu = 1;
    }
    if (lb) atomicOr(&f_bf16, 1);
    if (lf) atomicOr(&f_f32, 1);
    if (lu) atomicOr(&f_u8, 1);
    __syncthreads();
    if (threadIdx.x == 0)
        g_mask_mode = f_bf16 ? 3 : (f_f32 ? 1 : (f_u8 ? 0 : 2));
}

// ========== kernel 1a: split x into fp16 hi/lo ==========
__global__ void split_x_kernel(const float* __restrict__ x) {
    int i = blockIdx.x * blockDim.x + threadIdx.x;
    if (i >= B_ * IN_ / 4) return;
    float4 v = ((const float4*)x)[i];
    __half h[4], l[4];
    h[0] = __float2half_rn(v.x); l[0] = __float2half_rn(v.x - __half2float(h[0]));
    h[1] = __float2half_rn(v.y); l[1] = __float2half_rn(v.y - __half2float(h[1]));
    h[2] = __float2half_rn(v.z); l[2] = __float2half_rn(v.z - __half2float(h[2]));
    h[3] = __float2half_rn(v.w); l[3] = __float2half_rn(v.w - __half2float(h[3]));
    ((uint2*)g_xhi)[i] = *(uint2*)h;
    ((uint2*)g_xlo)[i] = *(uint2*)l;
}

// ========== kernel 1b: mask + split w1 (also store exact masked w) ==========
__global__ void split_w_kernel(const float* __restrict__ w1,
                               const void* __restrict__ mask) {
    int i = blockIdx.x * blockDim.x + threadIdx.x;
    if (i >= ND_ * IN_ / 4) return;
    int mode = g_mask_mode;
    float4 w = ((const float4*)w1)[i];
    bool m0, m1, m2, m3;
    if (mode == 0) {
        uchar4 mm = ((const uchar4*)mask)[i];
        m0 = mm.x; m1 = mm.y; m2 = mm.z; m3 = mm.w;
    } else if (mode == 1) {
        float4 mm = ((const float4*)mask)[i];
        m0 = mm.x != 0.f; m1 = mm.y != 0.f; m2 = mm.z != 0.f; m3 = mm.w != 0.f;
    } else if (mode == 2) {
        int4 mm = ((const int4*)mask)[i];
        m0 = mm.x != 0; m1 = mm.y != 0; m2 = mm.z != 0; m3 = mm.w != 0;
    } else {
        const __nv_bfloat16* mp = ((const __nv_bfloat16*)mask) + (size_t)i * 4;
        m0 = __bfloat162float(mp[0]) != 0.f; m1 = __bfloat162float(mp[1]) != 0.f;
        m2 = __bfloat162float(mp[2]) != 0.f; m3 = __bfloat162float(mp[3]) != 0.f;
    }
    w.x = m0 ? w.x : 0.f; w.y = m1 ? w.y : 0.f;
    w.z = m2 ? w.z : 0.f; w.w = m3 ? w.w : 0.f;
    ((float4*)g_w1m)[i] = w;
    __half h[4], l[4];
    h[0] = __float2half_rn(w.x); l[0] = __float2half_rn(w.x - __half2float(h[0]));
    h[1] = __float2half_rn(w.y); l[1] = __float2half_rn(w.y - __half2float(h[1]));
    h[2] = __float2half_rn(w.z); l[2] = __float2half_rn(w.z - __half2float(h[2]));
    h[3] = __float2half_rn(w.w); l[3] = __float2half_rn(w.w - __half2float(h[3]));
    ((uint2*)g_whi)[i] = *(uint2*)h;
    ((uint2*)g_wlo)[i] = *(uint2*)l;
}

// ========== kernel 2: wmma fp16 3-product GEMM, 3-stage pipeline ==========
#define GM_MT   128
#define GM_NT   256
#define GM_KC   32
#define NCHUNK  (IN_ / GM_KC)        // 32
#define ROWH    40                   // halfs per row (32 data + 8 pad)
#define ROWB    (ROWH * 2)           // 80 B

#define OFF_AHI 0
#define OFF_ALO (GM_MT * ROWB)                   // 10240
#define OFF_BHI (2 * GM_MT * ROWB)               // 20480
#define OFF_BLO (2 * GM_MT * ROWB + GM_NT * ROWB)// 40960
#define BUF_SZ  (2 * GM_MT * ROWB + 2 * GM_NT * ROWB)  // 61440
#define NSTAGE  3
#define GEMM_SMEM (NSTAGE * BUF_SZ)                    // 184320

__device__ __forceinline__ void stage_chunk(uint32_t sbuf, int tid,
                                            int m0, int n0, int k0) {
    const __half* Xhi = g_xhi; const __half* Xlo = g_xlo;
    const __half* Whi = g_whi; const __half* Wlo = g_wlo;
#pragma unroll
    for (int i = 0; i < 2; i++) {
        int v = tid + i * 256;
        int r = v >> 2, f = v & 3;
        uint32_t so = r * ROWB + f * 16;
        size_t g = (size_t)(m0 + r) * IN_ + k0 + f * 8;
        cp_async16(sbuf + OFF_AHI + so, &Xhi[g]);
        cp_async16(sbuf + OFF_ALO + so, &Xlo[g]);
    }
#pragma unroll
    for (int i = 0; i < 4; i++) {
        int v = tid + i * 256;
        int r = v >> 2, f = v & 3;
        uint32_t so = r * ROWB + f * 16;
        size_t g = (size_t)(n0 + r) * IN_ + k0 + f * 8;
        cp_async16(sbuf + OFF_BHI + so, &Whi[g]);
        cp_async16(sbuf + OFF_BLO + so, &Wlo[g]);
    }
}

__global__ void __launch_bounds__(256, 1)
gemm_fp16_kernel() {
    extern __shared__ char smem[];
    uint32_t sbase = smem_u32(smem);
    int tid = threadIdx.x;
    int wid = tid >> 5;
    int wm = wid & 1;
    int wn = wid >> 1;

    int ing   = blockIdx.x & 255;
    int ntile = (blockIdx.x >> 8) * 8 + (ing & 7);
    int mtile = ing >> 3;
    int m0 = mtile * GM_MT;
    int n0 = ntile * GM_NT;

    wmma::fragment<wmma::accumulator, 16, 16, 16, float> acc[4][4];
#pragma unroll
    for (int i = 0; i < 4; i++)
#pragma unroll
        for (int j = 0; j < 4; j++) wmma::fill_fragment(acc[i][j], 0.f);

    stage_chunk(sbase + 0 * BUF_SZ, tid, m0, n0, 0 * GM_KC);
    CP_COMMIT();
    stage_chunk(sbase + 1 * BUF_SZ, tid, m0, n0, 1 * GM_KC);
    CP_COMMIT();

    for (int it = 0; it < NCHUNK; ++it) {
        if (it + 2 < NCHUNK) {
            stage_chunk(sbase + ((it + 2) % NSTAGE) * BUF_SZ, tid, m0, n0, (it + 2) * GM_KC);
            CP_COMMIT();
            CP_WAIT_2();
        } else if (it + 1 < NCHUNK) {
            CP_WAIT_1();
        } else {
            CP_WAIT_0();
        }
        __syncthreads();

        const __half* buf = (const __half*)(smem + (it % NSTAGE) * BUF_SZ);
        const __half* Ah = buf + (OFF_AHI / 2) + wm * 64 * ROWH;
        const __half* Al = buf + (OFF_ALO / 2) + wm * 64 * ROWH;
        const __half* Bh = buf + (OFF_BHI / 2) + wn * 64 * ROWH;
        const __half* Bl = buf + (OFF_BLO / 2) + wn * 64 * ROWH;

#pragma unroll
        for (int ks = 0; ks < 2; ks++) {
            wmma::fragment<wmma::matrix_a, 16, 16, 16, __half, wmma::row_major> ah[4], al[4];
#pragma unroll
            for (int mt = 0; mt < 4; mt++) {
                wmma::load_matrix_sync(ah[mt], Ah + mt * 16 * ROWH + ks * 16, ROWH);
                wmma::load_matrix_sync(al[mt], Al + mt * 16 * ROWH + ks * 16, ROWH);
            }
#pragma unroll
            for (int nt = 0; nt < 4; nt++) {
                wmma::fragment<wmma::matrix_b, 16, 16, 16, __half, wmma::col_major> bh, bl;
                wmma::load_matrix_sync(bh, Bh + nt * 16 * ROWH + ks * 16, ROWH);
                wmma::load_matrix_sync(bl, Bl + nt * 16 * ROWH + ks * 16, ROWH);
#pragma unroll
                for (int mt = 0; mt < 4; mt++) {
                    wmma::mma_sync(acc[mt][nt], ah[mt], bh, acc[mt][nt]);
                    wmma::mma_sync(acc[mt][nt], ah[mt], bl, acc[mt][nt]);
                    wmma::mma_sync(acc[mt][nt], al[mt], bh, acc[mt][nt]);
                }
            }
        }
        __syncthreads();
    }

    float* base = g_h + (size_t)(m0 + wm * 64) * ND_ + n0 + wn * 64;
#pragma unroll
    for (int mt = 0; mt < 4; mt++)
#pragma unroll
        for (int nt = 0; nt < 4; nt++)
            wmma::store_matrix_sync(base + (size_t)mt * 16 * ND_ + nt * 16,
                                    acc[mt][nt], ND_, wmma::mem_row_major);
}

// ========== kernel 3: top-k + sequential-fp32 borderline fixup + output =====
__device__ __forceinline__ unsigned fkey(float f) {
    unsigned u = __float_as_uint(f);
    return (u & 0x80000000u) ? ~u : (u | 0x80000000u);
}
__device__ __forceinline__ float key2f(unsigned k) {
    unsigned u = (k & 0x80000000u) ? (k & 0x7FFFFFFFu) : ~k;
    return __uint_as_float(u);
}

#define BAND   2e-5f
#define SMAXN  64

__global__ void __launch_bounds__(256)
select_output_kernel(const float* __restrict__ H,
                     const float* __restrict__ x,
                     const float* __restrict__ b1,
                     const float* __restrict__ w2,
                     const float* __restrict__ b2,
                     float* __restrict__ out) {
    __shared__ float hs[ND_];            // 32 KB, h + bias
    __shared__ float xs[IN_];            // 4 KB, x row
    __shared__ unsigned int hist[256];
    __shared__ unsigned int scan[256];
    __shared__ unsigned int s_prefix;
    __shared__ int s_kk;
    __shared__ int sN, sK1;
    __shared__ int   S_idx[SMAXN];
    __shared__ float S_val[SMAXN];
    __shared__ unsigned char S_win[SMAXN];

    int b = blockIdx.x;
    int t = threadIdx.x;
    int lane = t & 31;

    // stage h + bias into smem; stage x row
    {
        const float4* hp = (const float4*)(H + (size_t)b * ND_);
        const float4* bp = (const float4*)b1;
        for (int i = t; i < ND_ / 4; i += 256) {
            float4 hv = hp[i];
            float4 bv = __ldg(bp + i);
            hv.x += bv.x; hv.y += bv.y; hv.z += bv.z; hv.w += bv.w;
            ((float4*)hs)[i] = hv;
        }
        const float4* xp = (const float4*)(x + (size_t)b * IN_);
        if (t < IN_ / 4) ((float4*)xs)[t] = __ldg(xp + t);
    }
    if (t == 0) { sN = 0; sK1 = 0; }
    __syncthreads();

    // ---- radix select: 4 passes, warp-aggregated histogram + parallel scan --
    unsigned prefix = 0;
    int kk = KWIN_;
#pragma unroll 1
    for (int pass = 0; pass < 4; pass++) {
        int shift = 24 - pass * 8;
        hist[t] = 0;
        __syncthreads();
        for (int i = t; i < ND_; i += 256) {
            unsigned u = fkey(hs[i]);
            bool cand = (pass == 0) || ((u >> (shift + 8)) == (prefix >> (shift + 8)));
            int bin = cand ? (int)((u >> shift) & 255u) : (256 + lane);
            unsigned mm = __match_any_sync(0xFFFFFFFFu, bin);
            if (bin < 256 && (int)(__ffs(mm) - 1) == lane)
                atomicAdd(&hist[bin], __popc(mm));
        }
        __syncthreads();
        // parallel suffix sums: scan[t] = sum_{j>=t} hist[j]
        scan[t] = hist[t];
        __syncthreads();
#pragma unroll
        for (int d = 1; d < 256; d <<= 1) {
            unsigned add = (t + d < 256) ? scan[t + d] : 0u;
            __syncthreads();
            scan[t] += add;
            __syncthreads();
        }
        unsigned sfx = scan[t];
        unsigned sfx_next = (t < 255) ? scan[t + 1] : 0u;
        if (sfx >= (unsigned)kk && sfx_next < (unsigned)kk) {
            s_prefix = prefix | ((unsigned)t << shift);
            s_kk = kk - (int)sfx_next;
        }
        __syncthreads();
        prefix = s_prefix;
        kk = s_kk;
        __syncthreads();
    }
    float thr_f = key2f(prefix);

    // ---- borderline detection ----
    int cert = 0;
    for (int i = t; i < ND_; i += 256) {
        float vv = hs[i];
        if (vv > thr_f + BAND) cert++;
        else if (vv >= thr_f - BAND) {
            int s = atomicAdd(&sN, 1);
            if (s < SMAXN) S_idx[s] = i;
        }
    }
    if (cert) atomicAdd(&sK1, cert);
    __syncthreads();
    int nS = sN < SMAXN ? sN : SMAXN;

    // L2-prefetch the w1m rows for all borderline elements (parallel)
    for (int s = 0; s < nS; s++) {
        const char* wr = (const char*)(g_w1m + (size_t)S_idx[s] * IN_);
        if (t < 32)
            asm volatile("prefetch.global.L2 [%0];" :: "l"(wr + t * 128));
    }
    __syncthreads();

    // exact fp32 recompute, ONE THREAD per element, strictly ascending-k
    // sequential FMA chain (bit-correlated with the reference; zero flips in R7).
    for (int s = t; s < nS; s += 256) {
        int j = S_idx[s];
        const float4* wr = (const float4*)(g_w1m + (size_t)j * IN_);
        float a = 0.f;
#pragma unroll 8
        for (int q = 0; q < IN_ / 4; q++) {
            float4 xv = *(const float4*)&xs[q * 4];
            float4 wv = __ldg(wr + q);
            a = fmaf(xv.x, wv.x, a);
            a = fmaf(xv.y, wv.y, a);
            a = fmaf(xv.z, wv.z, a);
            a = fmaf(xv.w, wv.w, a);
        }
        S_val[s] = a + __ldg(&b1[j]);
    }
    __syncthreads();
    if (t == 0) {
        int need = KWIN_ - sK1;
        for (int s = 0; s < nS; s++) S_win[s] = 0;
        for (int r = 0; r < need && r < nS; r++) {
            int best = -1;
            for (int s = 0; s < nS; s++) {
                if (S_win[s]) continue;
                if (best < 0 || S_val[s] > S_val[best] ||
                    (S_val[s] == S_val[best] && S_idx[s] < S_idx[best])) best = s;
            }
            if (best >= 0) S_win[best] = 1;
        }
    }
    __syncthreads();

    // ---- block-diagonal contraction: 2 outputs per thread ----
    for (int o = t; o < OD_; o += 256) {
        const float* w2p = w2 + (size_t)o * (DPC_ * OD_) + o * DPC_;
        float w[16];
        *(float4*)&w[0]  = __ldg((const float4*)(w2p + 0));
        *(float4*)&w[4]  = __ldg((const float4*)(w2p + 4));
        *(float4*)&w[8]  = __ldg((const float4*)(w2p + 8));
        *(float4*)&w[12] = __ldg((const float4*)(w2p + 12));
        float s_out = __ldg(&b2[o]);
#pragma unroll
        for (int d = 0; d < DPC_; d++) {
            int j = o * DPC_ + d;
            float val = hs[j];
            bool win;
            if (val > thr_f + BAND) win = true;
            else if (val >= thr_f - BAND) {
                win = false;
                bool found = false;
                for (int s = 0; s < nS; s++) {
                    if (S_idx[s] == j) {
                        win = (S_win[s] != 0);
                        val = S_val[s];
                        found = true;
                        break;
                    }
                }
                if (!found) win = (fkey(val) >= prefix);  // list-overflow fallback
            } else win = false;
            if (win) s_out += val * w[d];
        }
        out[(size_t)b * OD_ + o] = s_out;
    }
}

// ========== launcher ==========
extern "C" void kernel_launch(void* const* d_in, const int* in_sizes, int n_in,
                              void* d_out, int out_size) {
    const float* x   = (const float*)d_in[0];
    const float* w1  = (const float*)d_in[1];
    const float* b1  = (const float*)d_in[2];
    const void*  msk = d_in[3];
    const float* w2  = (const float*)d_in[4];
    const float* b2  = (const float*)d_in[5];
    float* out = (float*)d_out;

    float* h_ptr; cudaGetSymbolAddress((void**)&h_ptr, g_h);

    cudaFuncSetAttribute(gemm_fp16_kernel,
                         cudaFuncAttributeMaxDynamicSharedMemorySize, GEMM_SMEM);

    probe_mask_kernel<<<1, 256>>>((const unsigned int*)msk);
    split_x_kernel<<<(B_ * IN_ / 4 + 255) / 256, 256>>>(x);
    split_w_kernel<<<(ND_ * IN_ / 4 + 255) / 256, 256>>>(w1, msk);
    gemm_fp16_kernel<<<(B_ / GM_MT) * (ND_ / GM_NT), 256, GEMM_SMEM>>>();
    select_output_kernel<<<B_, 256>>>(h_ptr, x, b1, w2, b2, out);
}

// round 11
// speedup vs baseline: 2.8858x; 1.4391x over previous
#include <cuda_runtime.h>
#include <cuda_bf16.h>
#include <cuda_fp16.h>
#include <mma.h>
#include <stdint.h>

using namespace nvcuda;

// Problem dims
#define B_     4096
#define IN_    1024
#define ND_    8192
#define OD_    512
#define DPC_   16
#define KWIN_  819

// ---------------- device scratch ----------------
__device__ __align__(16) __half g_xhi[(size_t)B_ * IN_];    // 8 MB
__device__ __align__(16) __half g_xlo[(size_t)B_ * IN_];    // 8 MB
__device__ __align__(16) __half g_whi[(size_t)ND_ * IN_];   // 16 MB
__device__ __align__(16) __half g_wlo[(size_t)ND_ * IN_];   // 16 MB
__device__ __align__(16) float  g_w1m[(size_t)ND_ * IN_];   // 32 MB exact masked weights
__device__ __align__(16) float  g_h  [(size_t)B_ * ND_];    // 128 MB (no bias)
__device__ int   g_mask_mode;

__device__ __forceinline__ uint32_t smem_u32(const void* p) {
    uint32_t a;
    asm("{ .reg .u64 t; cvta.to.shared.u64 t, %1; cvt.u32.u64 %0, t; }" : "=r"(a) : "l"(p));
    return a;
}
__device__ __forceinline__ void cp_async16(uint32_t dst, const void* src) {
    asm volatile("cp.async.cg.shared.global [%0], [%1], 16;" :: "r"(dst), "l"(src));
}
#define CP_COMMIT()  asm volatile("cp.async.commit_group;" ::: "memory")
#define CP_WAIT_1()  asm volatile("cp.async.wait_group 1;" ::: "memory")
#define CP_WAIT_0()  asm volatile("cp.async.wait_group 0;" ::: "memory")

// ========== kernel 0: probe mask dtype (validated R1) ==========
__global__ void probe_mask_kernel(const unsigned int* __restrict__ m) {
    __shared__ int f_bf16, f_f32, f_u8;
    if (threadIdx.x == 0) { f_bf16 = 0; f_f32 = 0; f_u8 = 0; }
    __syncthreads();
    int lb = 0, lf = 0, lu = 0;
    for (int i = threadIdx.x; i < 4096; i += blockDim.x) {
        unsigned w = m[i];
        if (w == 0x00003F80u || w == 0x3F803F80u)   lb = 1;
        else if (w == 0x3F800000u)                  lf = 1;
        else if (w > 1u && (w & 0xFEFEFEFEu) == 0u) lu = 1;
    }
    if (lb) atomicOr(&f_bf16, 1);
    if (lf) atomicOr(&f_f32, 1);
    if (lu) atomicOr(&f_u8, 1);
    __syncthreads();
    if (threadIdx.x == 0)
        g_mask_mode = f_bf16 ? 3 : (f_f32 ? 1 : (f_u8 ? 0 : 2));
}

// ========== kernel 1a: split x into fp16 hi/lo ==========
__global__ void split_x_kernel(const float* __restrict__ x) {
    int i = blockIdx.x * blockDim.x + threadIdx.x;
    if (i >= B_ * IN_ / 4) return;
    float4 v = ((const float4*)x)[i];
    __half h[4], l[4];
    h[0] = __float2half_rn(v.x); l[0] = __float2half_rn(v.x - __half2float(h[0]));
    h[1] = __float2half_rn(v.y); l[1] = __float2half_rn(v.y - __half2float(h[1]));
    h[2] = __float2half_rn(v.z); l[2] = __float2half_rn(v.z - __half2float(h[2]));
    h[3] = __float2half_rn(v.w); l[3] = __float2half_rn(v.w - __half2float(h[3]));
    ((uint2*)g_xhi)[i] = *(uint2*)h;
    ((uint2*)g_xlo)[i] = *(uint2*)l;
}

// ========== kernel 1b: mask + split w1 (also store exact masked w) ==========
__global__ void split_w_kernel(const float* __restrict__ w1,
                               const void* __restrict__ mask) {
    int i = blockIdx.x * blockDim.x + threadIdx.x;
    if (i >= ND_ * IN_ / 4) return;
    int mode = g_mask_mode;
    float4 w = ((const float4*)w1)[i];
    bool m0, m1, m2, m3;
    if (mode == 0) {
        uchar4 mm = ((const uchar4*)mask)[i];
        m0 = mm.x; m1 = mm.y; m2 = mm.z; m3 = mm.w;
    } else if (mode == 1) {
        float4 mm = ((const float4*)mask)[i];
        m0 = mm.x != 0.f; m1 = mm.y != 0.f; m2 = mm.z != 0.f; m3 = mm.w != 0.f;
    } else if (mode == 2) {
        int4 mm = ((const int4*)mask)[i];
        m0 = mm.x != 0; m1 = mm.y != 0; m2 = mm.z != 0; m3 = mm.w != 0;
    } else {
        const __nv_bfloat16* mp = ((const __nv_bfloat16*)mask) + (size_t)i * 4;
        m0 = __bfloat162float(mp[0]) != 0.f; m1 = __bfloat162float(mp[1]) != 0.f;
        m2 = __bfloat162float(mp[2]) != 0.f; m3 = __bfloat162float(mp[3]) != 0.f;
    }
    w.x = m0 ? w.x : 0.f; w.y = m1 ? w.y : 0.f;
    w.z = m2 ? w.z : 0.f; w.w = m3 ? w.w : 0.f;
    ((float4*)g_w1m)[i] = w;
    __half h[4], l[4];
    h[0] = __float2half_rn(w.x); l[0] = __float2half_rn(w.x - __half2float(h[0]));
    h[1] = __float2half_rn(w.y); l[1] = __float2half_rn(w.y - __half2float(h[1]));
    h[2] = __float2half_rn(w.z); l[2] = __float2half_rn(w.z - __half2float(h[2]));
    h[3] = __float2half_rn(w.w); l[3] = __float2half_rn(w.w - __half2float(h[3]));
    ((uint2*)g_whi)[i] = *(uint2*)h;
    ((uint2*)g_wlo)[i] = *(uint2*)l;
}

// ========== kernel 2: wmma fp16 3-product GEMM, 512 threads ==========
// CTA 128x256, K-chunk 32, 16 warps (4/SMSP for latency hiding), warp tile 32x64.
#define GM_MT   128
#define GM_NT   256
#define GM_KC   32
#define NCHUNK  (IN_ / GM_KC)        // 32
#define ROWH    40                   // halfs per row (32 data + 8 pad)
#define ROWB    (ROWH * 2)           // 80 B

#define OFF_AHI 0
#define OFF_ALO (GM_MT * ROWB)                   // 10240
#define OFF_BHI (2 * GM_MT * ROWB)               // 20480
#define OFF_BLO (2 * GM_MT * ROWB + GM_NT * ROWB)// 40960
#define BUF_SZ  (2 * GM_MT * ROWB + 2 * GM_NT * ROWB)  // 61440
#define GEMM_SMEM (2 * BUF_SZ)                         // 122880

__device__ __forceinline__ void stage_chunk(uint32_t sbuf, int tid,
                                            int m0, int n0, int k0) {
    const __half* Xhi = g_xhi; const __half* Xlo = g_xlo;
    const __half* Whi = g_whi; const __half* Wlo = g_wlo;
    // A: 128 rows x 4 x 16B = 512 slots (1 per thread)
    {
        int r = tid >> 2, f = tid & 3;
        uint32_t so = r * ROWB + f * 16;
        size_t g = (size_t)(m0 + r) * IN_ + k0 + f * 8;
        cp_async16(sbuf + OFF_AHI + so, &Xhi[g]);
        cp_async16(sbuf + OFF_ALO + so, &Xlo[g]);
    }
    // B: 256 rows x 4 x 16B = 1024 slots (2 per thread)
#pragma unroll
    for (int i = 0; i < 2; i++) {
        int v = tid + i * 512;
        int r = v >> 2, f = v & 3;
        uint32_t so = r * ROWB + f * 16;
        size_t g = (size_t)(n0 + r) * IN_ + k0 + f * 8;
        cp_async16(sbuf + OFF_BHI + so, &Whi[g]);
        cp_async16(sbuf + OFF_BLO + so, &Wlo[g]);
    }
}

__global__ void __launch_bounds__(512, 1)
gemm_fp16_kernel() {
    extern __shared__ char smem[];
    uint32_t sbase = smem_u32(smem);
    int tid = threadIdx.x;
    int wid = tid >> 5;
    int wn = wid & 3;          // 4 n-slices of 64
    int wm = wid >> 2;         // 4 m-slices of 32

    int ing   = blockIdx.x & 255;
    int ntile = (blockIdx.x >> 8) * 8 + (ing & 7);
    int mtile = ing >> 3;
    int m0 = mtile * GM_MT;
    int n0 = ntile * GM_NT;

    wmma::fragment<wmma::accumulator, 16, 16, 16, float> acc[2][4];
#pragma unroll
    for (int i = 0; i < 2; i++)
#pragma unroll
        for (int j = 0; j < 4; j++) wmma::fill_fragment(acc[i][j], 0.f);

    stage_chunk(sbase, tid, m0, n0, 0);
    CP_COMMIT();

    for (int it = 0; it < NCHUNK; ++it) {
        if (it + 1 < NCHUNK) {
            stage_chunk(sbase + ((it + 1) & 1) * BUF_SZ, tid, m0, n0, (it + 1) * GM_KC);
            CP_COMMIT();
            CP_WAIT_1();
        } else {
            CP_WAIT_0();
        }
        __syncthreads();

        const __half* buf = (const __half*)(smem + (it & 1) * BUF_SZ);
        const __half* Ah = buf + (OFF_AHI / 2) + wm * 32 * ROWH;
        const __half* Al = buf + (OFF_ALO / 2) + wm * 32 * ROWH;
        const __half* Bh = buf + (OFF_BHI / 2) + wn * 64 * ROWH;
        const __half* Bl = buf + (OFF_BLO / 2) + wn * 64 * ROWH;

#pragma unroll
        for (int ks = 0; ks < 2; ks++) {
            wmma::fragment<wmma::matrix_a, 16, 16, 16, __half, wmma::row_major> ah[2], al[2];
#pragma unroll
            for (int mt = 0; mt < 2; mt++) {
                wmma::load_matrix_sync(ah[mt], Ah + mt * 16 * ROWH + ks * 16, ROWH);
                wmma::load_matrix_sync(al[mt], Al + mt * 16 * ROWH + ks * 16, ROWH);
            }
#pragma unroll
            for (int nt = 0; nt < 4; nt++) {
                wmma::fragment<wmma::matrix_b, 16, 16, 16, __half, wmma::col_major> bh, bl;
                wmma::load_matrix_sync(bh, Bh + nt * 16 * ROWH + ks * 16, ROWH);
                wmma::load_matrix_sync(bl, Bl + nt * 16 * ROWH + ks * 16, ROWH);
#pragma unroll
                for (int mt = 0; mt < 2; mt++) {
                    wmma::mma_sync(acc[mt][nt], ah[mt], bh, acc[mt][nt]);
                    wmma::mma_sync(acc[mt][nt], ah[mt], bl, acc[mt][nt]);
                    wmma::mma_sync(acc[mt][nt], al[mt], bh, acc[mt][nt]);
                }
            }
        }
        __syncthreads();
    }

    float* base = g_h + (size_t)(m0 + wm * 32) * ND_ + n0 + wn * 64;
#pragma unroll
    for (int mt = 0; mt < 2; mt++)
#pragma unroll
        for (int nt = 0; nt < 4; nt++)
            wmma::store_matrix_sync(base + (size_t)mt * 16 * ND_ + nt * 16,
                                    acc[mt][nt], ND_, wmma::mem_row_major);
}

// ========== kernel 3: top-k + sequential-fp32 borderline fixup + output =====
__device__ __forceinline__ unsigned fkey(float f) {
    unsigned u = __float_as_uint(f);
    return (u & 0x80000000u) ? ~u : (u | 0x80000000u);
}
__device__ __forceinline__ float key2f(unsigned k) {
    unsigned u = (k & 0x80000000u) ? (k & 0x7FFFFFFFu) : ~k;
    return __uint_as_float(u);
}

#define BAND   2e-5f
#define SMAXN  64

__global__ void __launch_bounds__(256)
select_output_kernel(const float* __restrict__ H,
                     const float* __restrict__ x,
                     const float* __restrict__ b1,
                     const float* __restrict__ w2,
                     const float* __restrict__ b2,
                     float* __restrict__ out) {
    __shared__ float hs[ND_];            // 32 KB, h + bias
    __shared__ float xs[IN_];            // 4 KB, x row
    __shared__ unsigned int hist[256];
    __shared__ unsigned int s_prefix;
    __shared__ int s_kk;
    __shared__ int sN, sK1;
    __shared__ int   S_idx[SMAXN];
    __shared__ float S_val[SMAXN];
    __shared__ unsigned char S_win[SMAXN];

    int b = blockIdx.x;
    int t = threadIdx.x;

    // stage h + bias into smem; stage x row
    {
        const float4* hp = (const float4*)(H + (size_t)b * ND_);
        const float4* bp = (const float4*)b1;
        for (int i = t; i < ND_ / 4; i += 256) {
            float4 hv = hp[i];
            float4 bv = __ldg(bp + i);
            hv.x += bv.x; hv.y += bv.y; hv.z += bv.z; hv.w += bv.w;
            ((float4*)hs)[i] = hv;
        }
        const float4* xp = (const float4*)(x + (size_t)b * IN_);
        if (t < IN_ / 4) ((float4*)xs)[t] = __ldg(xp + t);
    }
    if (t == 0) { sN = 0; sK1 = 0; }
    __syncthreads();

    // ---- radix select: 4 passes, plain smem atomics (R1-proven) ----
    unsigned prefix = 0;
    int kk = KWIN_;
#pragma unroll 1
    for (int pass = 0; pass < 4; pass++) {
        int shift = 24 - pass * 8;
        hist[t] = 0;
        __syncthreads();
        for (int i = t; i < ND_; i += 256) {
            unsigned u = fkey(hs[i]);
            bool cand = (pass == 0) || ((u >> (shift + 8)) == (prefix >> (shift + 8)));
            if (cand) atomicAdd(&hist[(u >> shift) & 255u], 1u);
        }
        __syncthreads();
        if (t == 0) {
            unsigned cum = 0; int bin = 255;
            for (; bin > 0; bin--) {
                unsigned c = hist[bin];
                if (cum + c >= (unsigned)kk) break;
                cum += c;
            }
            s_prefix = prefix | ((unsigned)bin << shift);
            s_kk = kk - (int)cum;
        }
        __syncthreads();
        prefix = s_prefix;
        kk = s_kk;
        __syncthreads();
    }
    float thr_f = key2f(prefix);

    // ---- borderline detection ----
    int cert = 0;
    for (int i = t; i < ND_; i += 256) {
        float vv = hs[i];
        if (vv > thr_f + BAND) cert++;
        else if (vv >= thr_f - BAND) {
            int s = atomicAdd(&sN, 1);
            if (s < SMAXN) S_idx[s] = i;
        }
    }
    if (cert) atomicAdd(&sK1, cert);
    __syncthreads();
    int nS = sN < SMAXN ? sN : SMAXN;

    // exact fp32 recompute, ONE THREAD per element, strictly ascending-k
    // sequential FMA chain (bit-correlated with the reference; zero flips R7/R9).
    for (int s = t; s < nS; s += 256) {
        int j = S_idx[s];
        const float4* wr = (const float4*)(g_w1m + (size_t)j * IN_);
        float a = 0.f;
#pragma unroll 8
        for (int q = 0; q < IN_ / 4; q++) {
            float4 xv = *(const float4*)&xs[q * 4];
            float4 wv = __ldg(wr + q);
            a = fmaf(xv.x, wv.x, a);
            a = fmaf(xv.y, wv.y, a);
            a = fmaf(xv.z, wv.z, a);
            a = fmaf(xv.w, wv.w, a);
        }
        S_val[s] = a + __ldg(&b1[j]);
    }
    __syncthreads();
    if (t == 0) {
        int need = KWIN_ - sK1;
        for (int s = 0; s < nS; s++) S_win[s] = 0;
        for (int r = 0; r < need && r < nS; r++) {
            int best = -1;
            for (int s = 0; s < nS; s++) {
                if (S_win[s]) continue;
                if (best < 0 || S_val[s] > S_val[best] ||
                    (S_val[s] == S_val[best] && S_idx[s] < S_idx[best])) best = s;
            }
            if (best >= 0) S_win[best] = 1;
        }
    }
    __syncthreads();

    // ---- block-diagonal contraction: 2 outputs per thread ----
    for (int o = t; o < OD_; o += 256) {
        const float* w2p = w2 + (size_t)o * (DPC_ * OD_) + o * DPC_;
        float w[16];
        *(float4*)&w[0]  = __ldg((const float4*)(w2p + 0));
        *(float4*)&w[4]  = __ldg((const float4*)(w2p + 4));
        *(float4*)&w[8]  = __ldg((const float4*)(w2p + 8));
        *(float4*)&w[12] = __ldg((const float4*)(w2p + 12));
        float s_out = __ldg(&b2[o]);
#pragma unroll
        for (int d = 0; d < DPC_; d++) {
            int j = o * DPC_ + d;
            float val = hs[j];
            bool win;
            if (val > thr_f + BAND) win = true;
            else if (val >= thr_f - BAND) {
                win = false;
                bool found = false;
                for (int s = 0; s < nS; s++) {
                    if (S_idx[s] == j) {
                        win = (S_win[s] != 0);
                        val = S_val[s];
                        found = true;
                        break;
                    }
                }
                if (!found) win = (fkey(val) >= prefix);  // list-overflow fallback
            } else win = false;
            if (win) s_out += val * w[d];
        }
        out[(size_t)b * OD_ + o] = s_out;
    }
}

// ========== launcher ==========
extern "C" void kernel_launch(void* const* d_in, const int* in_sizes, int n_in,
                              void* d_out, int out_size) {
    const float* x   = (const float*)d_in[0];
    const float* w1  = (const float*)d_in[1];
    const float* b1  = (const float*)d_in[2];
    const void*  msk = d_in[3];
    const float* w2  = (const float*)d_in[4];
    const float* b2  = (const float*)d_in[5];
    float* out = (float*)d_out;

    float* h_ptr; cudaGetSymbolAddress((void**)&h_ptr, g_h);

    cudaFuncSetAttribute(gemm_fp16_kernel,
                         cudaFuncAttributeMaxDynamicSharedMemorySize, GEMM_SMEM);

    probe_mask_kernel<<<1, 256>>>((const unsigned int*)msk);
    split_x_kernel<<<(B_ * IN_ / 4 + 255) / 256, 256>>>(x);
    split_w_kernel<<<(ND_ * IN_ / 4 + 255) / 256, 256>>>(w1, msk);
    gemm_fp16_kernel<<<(B_ / GM_MT) * (ND_ / GM_NT), 512, GEMM_SMEM>>>();
    select_output_kernel<<<B_, 256>>>(h_ptr, x, b1, w2, b2, out);
}

// round 13
// speedup vs baseline: 3.0992x; 1.0740x over previous
#include <cuda_runtime.h>
#include <cuda_bf16.h>
#include <cuda_fp16.h>
#include <mma.h>
#include <stdint.h>

using namespace nvcuda;

// Problem dims
#define B_     4096
#define IN_    1024
#define ND_    8192
#define OD_    512
#define DPC_   16
#define KWIN_  819

// ---------------- device scratch ----------------
__device__ __align__(16) __half g_xhi[(size_t)B_ * IN_];    // 8 MB
__device__ __align__(16) __half g_xlo[(size_t)B_ * IN_];    // 8 MB
__device__ __align__(16) __half g_whi[(size_t)ND_ * IN_];   // 16 MB
__device__ __align__(16) __half g_wlo[(size_t)ND_ * IN_];   // 16 MB
__device__ __align__(16) float  g_w1m[(size_t)ND_ * IN_];   // 32 MB exact masked weights
__device__ __align__(16) float  g_h  [(size_t)B_ * ND_];    // 128 MB (no bias)
__device__ int   g_mask_mode;

__device__ __forceinline__ uint32_t smem_u32(const void* p) {
    uint32_t a;
    asm("{ .reg .u64 t; cvta.to.shared.u64 t, %1; cvt.u32.u64 %0, t; }" : "=r"(a) : "l"(p));
    return a;
}
__device__ __forceinline__ void cp_async16(uint32_t dst, const void* src) {
    asm volatile("cp.async.cg.shared.global [%0], [%1], 16;" :: "r"(dst), "l"(src));
}
#define CP_COMMIT()  asm volatile("cp.async.commit_group;" ::: "memory")
#define CP_WAIT_1()  asm volatile("cp.async.wait_group 1;" ::: "memory")
#define CP_WAIT_0()  asm volatile("cp.async.wait_group 0;" ::: "memory")

// ========== kernel 0: probe mask dtype (validated R1) ==========
__global__ void probe_mask_kernel(const unsigned int* __restrict__ m) {
    __shared__ int f_bf16, f_f32, f_u8;
    if (threadIdx.x == 0) { f_bf16 = 0; f_f32 = 0; f_u8 = 0; }
    __syncthreads();
    int lb = 0, lf = 0, lu = 0;
    for (int i = threadIdx.x; i < 4096; i += blockDim.x) {
        unsigned w = m[i];
        if (w == 0x00003F80u || w == 0x3F803F80u)   lb = 1;
        else if (w == 0x3F800000u)                  lf = 1;
        else if (w > 1u && (w & 0xFEFEFEFEu) == 0u) lu = 1;
    }
    if (lb) atomicOr(&f_bf16, 1);
    if (lf) atomicOr(&f_f32, 1);
    if (lu) atomicOr(&f_u8, 1);
    __syncthreads();
    if (threadIdx.x == 0)
        g_mask_mode = f_bf16 ? 3 : (f_f32 ? 1 : (f_u8 ? 0 : 2));
}

// ========== kernel 1a: split x into fp16 hi/lo ==========
__global__ void split_x_kernel(const float* __restrict__ x) {
    int i = blockIdx.x * blockDim.x + threadIdx.x;
    if (i >= B_ * IN_ / 4) return;
    float4 v = ((const float4*)x)[i];
    __half h[4], l[4];
    h[0] = __float2half_rn(v.x); l[0] = __float2half_rn(v.x - __half2float(h[0]));
    h[1] = __float2half_rn(v.y); l[1] = __float2half_rn(v.y - __half2float(h[1]));
    h[2] = __float2half_rn(v.z); l[2] = __float2half_rn(v.z - __half2float(h[2]));
    h[3] = __float2half_rn(v.w); l[3] = __float2half_rn(v.w - __half2float(h[3]));
    ((uint2*)g_xhi)[i] = *(uint2*)h;
    ((uint2*)g_xlo)[i] = *(uint2*)l;
}

// ========== kernel 1b: mask + split w1 (also store exact masked w) ==========
__global__ void split_w_kernel(const float* __restrict__ w1,
                               const void* __restrict__ mask) {
    int i = blockIdx.x * blockDim.x + threadIdx.x;
    if (i >= ND_ * IN_ / 4) return;
    int mode = g_mask_mode;
    float4 w = ((const float4*)w1)[i];
    bool m0, m1, m2, m3;
    if (mode == 0) {
        uchar4 mm = ((const uchar4*)mask)[i];
        m0 = mm.x; m1 = mm.y; m2 = mm.z; m3 = mm.w;
    } else if (mode == 1) {
        float4 mm = ((const float4*)mask)[i];
        m0 = mm.x != 0.f; m1 = mm.y != 0.f; m2 = mm.z != 0.f; m3 = mm.w != 0.f;
    } else if (mode == 2) {
        int4 mm = ((const int4*)mask)[i];
        m0 = mm.x != 0; m1 = mm.y != 0; m2 = mm.z != 0; m3 = mm.w != 0;
    } else {
        const __nv_bfloat16* mp = ((const __nv_bfloat16*)mask) + (size_t)i * 4;
        m0 = __bfloat162float(mp[0]) != 0.f; m1 = __bfloat162float(mp[1]) != 0.f;
        m2 = __bfloat162float(mp[2]) != 0.f; m3 = __bfloat162float(mp[3]) != 0.f;
    }
    w.x = m0 ? w.x : 0.f; w.y = m1 ? w.y : 0.f;
    w.z = m2 ? w.z : 0.f; w.w = m3 ? w.w : 0.f;
    ((float4*)g_w1m)[i] = w;
    __half h[4], l[4];
    h[0] = __float2half_rn(w.x); l[0] = __float2half_rn(w.x - __half2float(h[0]));
    h[1] = __float2half_rn(w.y); l[1] = __float2half_rn(w.y - __half2float(h[1]));
    h[2] = __float2half_rn(w.z); l[2] = __float2half_rn(w.z - __half2float(h[2]));
    h[3] = __float2half_rn(w.w); l[3] = __float2half_rn(w.w - __half2float(h[3]));
    ((uint2*)g_whi)[i] = *(uint2*)h;
    ((uint2*)g_wlo)[i] = *(uint2*)l;
}

// ========== kernel 2: wmma fp16 3-product GEMM, 2 CTAs/SM ==========
// CTA 128x128, K-chunk 32, 256 threads (8 warps), warp tile 32x64,
// double-buffered (82 KB smem) so TWO CTAs co-reside per SM and cover each
// other's barrier/staging stalls.
#define GM_MT   128
#define GM_NT   128
#define GM_KC   32
#define NCHUNK  (IN_ / GM_KC)        // 32
#define ROWH    40                   // halfs per row (32 data + 8 pad)
#define ROWB    (ROWH * 2)           // 80 B

#define OFF_AHI 0
#define OFF_ALO (GM_MT * ROWB)                   // 10240
#define OFF_BHI (2 * GM_MT * ROWB)               // 20480
#define OFF_BLO (2 * GM_MT * ROWB + GM_NT * ROWB)// 30720
#define BUF_SZ  (2 * GM_MT * ROWB + 2 * GM_NT * ROWB)  // 40960
#define GEMM_SMEM (2 * BUF_SZ)                         // 81920

__device__ __forceinline__ void stage_chunk(uint32_t sbuf, int tid,
                                            int m0, int n0, int k0) {
    const __half* Xhi = g_xhi; const __half* Xlo = g_xlo;
    const __half* Whi = g_whi; const __half* Wlo = g_wlo;
    // A: 128 rows x 4 x 16B = 512 slots (2 per thread)
#pragma unroll
    for (int i = 0; i < 2; i++) {
        int v = tid + i * 256;
        int r = v >> 2, f = v & 3;
        uint32_t so = r * ROWB + f * 16;
        size_t g = (size_t)(m0 + r) * IN_ + k0 + f * 8;
        cp_async16(sbuf + OFF_AHI + so, &Xhi[g]);
        cp_async16(sbuf + OFF_ALO + so, &Xlo[g]);
    }
    // B: 128 rows x 4 x 16B = 512 slots (2 per thread)
#pragma unroll
    for (int i = 0; i < 2; i++) {
        int v = tid + i * 256;
        int r = v >> 2, f = v & 3;
        uint32_t so = r * ROWB + f * 16;
        size_t g = (size_t)(n0 + r) * IN_ + k0 + f * 8;
        cp_async16(sbuf + OFF_BHI + so, &Whi[g]);
        cp_async16(sbuf + OFF_BLO + so, &Wlo[g]);
    }
}

__global__ void __launch_bounds__(256, 2)
gemm_fp16_kernel() {
    extern __shared__ char smem[];
    uint32_t sbase = smem_u32(smem);
    int tid = threadIdx.x;
    int wid = tid >> 5;
    int wm = wid & 3;          // 4 m-slices of 32
    int wn = wid >> 2;         // 2 n-slices of 64

    // swizzle: groups of (8 ntiles x 32 mtiles) = 256 CTAs -> B panel + all A in L2
    int ing   = blockIdx.x & 255;
    int ntile = (blockIdx.x >> 8) * 8 + (ing & 7);
    int mtile = ing >> 3;
    int m0 = mtile * GM_MT;
    int n0 = ntile * GM_NT;

    wmma::fragment<wmma::accumulator, 16, 16, 16, float> acc[2][4];
#pragma unroll
    for (int i = 0; i < 2; i++)
#pragma unroll
        for (int j = 0; j < 4; j++) wmma::fill_fragment(acc[i][j], 0.f);

    stage_chunk(sbase, tid, m0, n0, 0);
    CP_COMMIT();

    for (int it = 0; it < NCHUNK; ++it) {
        if (it + 1 < NCHUNK) {
            stage_chunk(sbase + ((it + 1) & 1) * BUF_SZ, tid, m0, n0, (it + 1) * GM_KC);
            CP_COMMIT();
            CP_WAIT_1();
        } else {
            CP_WAIT_0();
        }
        __syncthreads();

        const __half* buf = (const __half*)(smem + (it & 1) * BUF_SZ);
        const __half* Ah = buf + (OFF_AHI / 2) + wm * 32 * ROWH;
        const __half* Al = buf + (OFF_ALO / 2) + wm * 32 * ROWH;
        const __half* Bh = buf + (OFF_BHI / 2) + wn * 64 * ROWH;
        const __half* Bl = buf + (OFF_BLO / 2) + wn * 64 * ROWH;

#pragma unroll
        for (int ks = 0; ks < 2; ks++) {
            wmma::fragment<wmma::matrix_a, 16, 16, 16, __half, wmma::row_major> ah[2], al[2];
#pragma unroll
            for (int mt = 0; mt < 2; mt++) {
                wmma::load_matrix_sync(ah[mt], Ah + mt * 16 * ROWH + ks * 16, ROWH);
                wmma::load_matrix_sync(al[mt], Al + mt * 16 * ROWH + ks * 16, ROWH);
            }
#pragma unroll
            for (int nt = 0; nt < 4; nt++) {
                wmma::fragment<wmma::matrix_b, 16, 16, 16, __half, wmma::col_major> bh, bl;
                wmma::load_matrix_sync(bh, Bh + nt * 16 * ROWH + ks * 16, ROWH);
                wmma::load_matrix_sync(bl, Bl + nt * 16 * ROWH + ks * 16, ROWH);
#pragma unroll
                for (int mt = 0; mt < 2; mt++) {
                    wmma::mma_sync(acc[mt][nt], ah[mt], bh, acc[mt][nt]);
                    wmma::mma_sync(acc[mt][nt], ah[mt], bl, acc[mt][nt]);
                    wmma::mma_sync(acc[mt][nt], al[mt], bh, acc[mt][nt]);
                }
            }
        }
        __syncthreads();
    }

    float* base = g_h + (size_t)(m0 + wm * 32) * ND_ + n0 + wn * 64;
#pragma unroll
    for (int mt = 0; mt < 2; mt++)
#pragma unroll
        for (int nt = 0; nt < 4; nt++)
            wmma::store_matrix_sync(base + (size_t)mt * 16 * ND_ + nt * 16,
                                    acc[mt][nt], ND_, wmma::mem_row_major);
}

// ========== kernel 3: top-k + sequential-fp32 borderline fixup + output =====
__device__ __forceinline__ unsigned fkey(float f) {
    unsigned u = __float_as_uint(f);
    return (u & 0x80000000u) ? ~u : (u | 0x80000000u);
}
__device__ __forceinline__ float key2f(unsigned k) {
    unsigned u = (k & 0x80000000u) ? (k & 0x7FFFFFFFu) : ~k;
    return __uint_as_float(u);
}

#define BAND   2e-5f
#define SMAXN  64

__global__ void __launch_bounds__(256)
select_output_kernel(const float* __restrict__ H,
                     const float* __restrict__ x,
                     const float* __restrict__ b1,
                     const float* __restrict__ w2,
                     const float* __restrict__ b2,
                     float* __restrict__ out) {
    __shared__ float hs[ND_];            // 32 KB, h + bias
    __shared__ float xs[IN_];            // 4 KB, x row
    __shared__ unsigned int hist[256];
    __shared__ unsigned int s_prefix;
    __shared__ int s_kk;
    __shared__ int sN, sK1;
    __shared__ int   S_idx[SMAXN];
    __shared__ float S_val[SMAXN];
    __shared__ unsigned char S_win[SMAXN];

    int b = blockIdx.x;
    int t = threadIdx.x;

    // stage h + bias into smem; stage x row
    {
        const float4* hp = (const float4*)(H + (size_t)b * ND_);
        const float4* bp = (const float4*)b1;
        for (int i = t; i < ND_ / 4; i += 256) {
            float4 hv = hp[i];
            float4 bv = __ldg(bp + i);
            hv.x += bv.x; hv.y += bv.y; hv.z += bv.z; hv.w += bv.w;
            ((float4*)hs)[i] = hv;
        }
        const float4* xp = (const float4*)(x + (size_t)b * IN_);
        if (t < IN_ / 4) ((float4*)xs)[t] = __ldg(xp + t);
    }
    if (t == 0) { sN = 0; sK1 = 0; }
    __syncthreads();

    // ---- radix select: 4 passes, plain smem atomics (R1-proven) ----
    unsigned prefix = 0;
    int kk = KWIN_;
#pragma unroll 1
    for (int pass = 0; pass < 4; pass++) {
        int shift = 24 - pass * 8;
        hist[t] = 0;
        __syncthreads();
        for (int i = t; i < ND_; i += 256) {
            unsigned u = fkey(hs[i]);
            bool cand = (pass == 0) || ((u >> (shift + 8)) == (prefix >> (shift + 8)));
            if (cand) atomicAdd(&hist[(u >> shift) & 255u], 1u);
        }
        __syncthreads();
        if (t == 0) {
            unsigned cum = 0; int bin = 255;
            for (; bin > 0; bin--) {
                unsigned c = hist[bin];
                if (cum + c >= (unsigned)kk) break;
                cum += c;
            }
            s_prefix = prefix | ((unsigned)bin << shift);
            s_kk = kk - (int)cum;
        }
        __syncthreads();
        prefix = s_prefix;
        kk = s_kk;
        __syncthreads();
    }
    float thr_f = key2f(prefix);

    // ---- borderline detection ----
    int cert = 0;
    for (int i = t; i < ND_; i += 256) {
        float vv = hs[i];
        if (vv > thr_f + BAND) cert++;
        else if (vv >= thr_f - BAND) {
            int s = atomicAdd(&sN, 1);
            if (s < SMAXN) S_idx[s] = i;
        }
    }
    if (cert) atomicAdd(&sK1, cert);
    __syncthreads();
    int nS = sN < SMAXN ? sN : SMAXN;

    // exact fp32 recompute, ONE THREAD per element, strictly ascending-k
    // sequential FMA chain (bit-correlated with the reference; zero flips R7/R9/R11).
    for (int s = t; s < nS; s += 256) {
        int j = S_idx[s];
        const float4* wr = (const float4*)(g_w1m + (size_t)j * IN_);
        float a = 0.f;
#pragma unroll 8
        for (int q = 0; q < IN_ / 4; q++) {
            float4 xv = *(const float4*)&xs[q * 4];
            float4 wv = __ldg(wr + q);
            a = fmaf(xv.x, wv.x, a);
            a = fmaf(xv.y, wv.y, a);
            a = fmaf(xv.z, wv.z, a);
            a = fmaf(xv.w, wv.w, a);
        }
        S_val[s] = a + __ldg(&b1[j]);
    }
    __syncthreads();
    if (t == 0) {
        int need = KWIN_ - sK1;
        for (int s = 0; s < nS; s++) S_win[s] = 0;
        for (int r = 0; r < need && r < nS; r++) {
            int best = -1;
            for (int s = 0; s < nS; s++) {
                if (S_win[s]) continue;
                if (best < 0 || S_val[s] > S_val[best] ||
                    (S_val[s] == S_val[best] && S_idx[s] < S_idx[best])) best = s;
            }
            if (best >= 0) S_win[best] = 1;
        }
    }
    __syncthreads();

    // ---- block-diagonal contraction: 2 outputs per thread ----
    for (int o = t; o < OD_; o += 256) {
        const float* w2p = w2 + (size_t)o * (DPC_ * OD_) + o * DPC_;
        float w[16];
        *(float4*)&w[0]  = __ldg((const float4*)(w2p + 0));
        *(float4*)&w[4]  = __ldg((const float4*)(w2p + 4));
        *(float4*)&w[8]  = __ldg((const float4*)(w2p + 8));
        *(float4*)&w[12] = __ldg((const float4*)(w2p + 12));
        float s_out = __ldg(&b2[o]);
#pragma unroll
        for (int d = 0; d < DPC_; d++) {
            int j = o * DPC_ + d;
            float val = hs[j];
            bool win;
            if (val > thr_f + BAND) win = true;
            else if (val >= thr_f - BAND) {
                win = false;
                bool found = false;
                for (int s = 0; s < nS; s++) {
                    if (S_idx[s] == j) {
                        win = (S_win[s] != 0);
                        val = S_val[s];
                        found = true;
                        break;
                    }
                }
                if (!found) win = (fkey(val) >= prefix);  // list-overflow fallback
            } else win = false;
            if (win) s_out += val * w[d];
        }
        out[(size_t)b * OD_ + o] = s_out;
    }
}

// ========== launcher ==========
extern "C" void kernel_launch(void* const* d_in, const int* in_sizes, int n_in,
                              void* d_out, int out_size) {
    const float* x   = (const float*)d_in[0];
    const float* w1  = (const float*)d_in[1];
    const float* b1  = (const float*)d_in[2];
    const void*  msk = d_in[3];
    const float* w2  = (const float*)d_in[4];
    const float* b2  = (const float*)d_in[5];
    float* out = (float*)d_out;

    float* h_ptr; cudaGetSymbolAddress((void**)&h_ptr, g_h);

    cudaFuncSetAttribute(gemm_fp16_kernel,
                         cudaFuncAttributeMaxDynamicSharedMemorySize, GEMM_SMEM);

    probe_mask_kernel<<<1, 256>>>((const unsigned int*)msk);
    split_x_kernel<<<(B_ * IN_ / 4 + 255) / 256, 256>>>(x);
    split_w_kernel<<<(ND_ * IN_ / 4 + 255) / 256, 256>>>(w1, msk);
    gemm_fp16_kernel<<<(B_ / GM_MT) * (ND_ / GM_NT), 256, GEMM_SMEM>>>();
    select_output_kernel<<<B_, 256>>>(h_ptr, x, b1, w2, b2, out);
}

// round 14
// speedup vs baseline: 3.5930x; 1.1593x over previous
#include <cuda_runtime.h>
#include <cuda_bf16.h>
#include <cuda_fp16.h>
#include <mma.h>
#include <stdint.h>

using namespace nvcuda;

// Problem dims
#define B_     4096
#define IN_    1024
#define ND_    8192
#define OD_    512
#define DPC_   16
#define KWIN_  819

// ---------------- device scratch ----------------
__device__ __align__(16) __half g_xhi[(size_t)B_ * IN_];    // 8 MB
__device__ __align__(16) __half g_xlo[(size_t)B_ * IN_];    // 8 MB
__device__ __align__(16) __half g_whi[(size_t)ND_ * IN_];   // 16 MB
__device__ __align__(16) float  g_w1m[(size_t)ND_ * IN_];   // 32 MB exact masked weights
__device__ __align__(16) float  g_h  [(size_t)B_ * ND_];    // 128 MB (no bias)
__device__ int   g_mask_mode;

__device__ __forceinline__ uint32_t smem_u32(const void* p) {
    uint32_t a;
    asm("{ .reg .u64 t; cvta.to.shared.u64 t, %1; cvt.u32.u64 %0, t; }" : "=r"(a) : "l"(p));
    return a;
}
__device__ __forceinline__ void cp_async16(uint32_t dst, const void* src) {
    asm volatile("cp.async.cg.shared.global [%0], [%1], 16;" :: "r"(dst), "l"(src));
}
#define CP_COMMIT()  asm volatile("cp.async.commit_group;" ::: "memory")
#define CP_WAIT_1()  asm volatile("cp.async.wait_group 1;" ::: "memory")
#define CP_WAIT_0()  asm volatile("cp.async.wait_group 0;" ::: "memory")

// ========== kernel 0: probe mask dtype (validated R1) ==========
__global__ void probe_mask_kernel(const unsigned int* __restrict__ m) {
    __shared__ int f_bf16, f_f32, f_u8;
    if (threadIdx.x == 0) { f_bf16 = 0; f_f32 = 0; f_u8 = 0; }
    __syncthreads();
    int lb = 0, lf = 0, lu = 0;
    for (int i = threadIdx.x; i < 4096; i += blockDim.x) {
        unsigned w = m[i];
        if (w == 0x00003F80u || w == 0x3F803F80u)   lb = 1;
        else if (w == 0x3F800000u)                  lf = 1;
        else if (w > 1u && (w & 0xFEFEFEFEu) == 0u) lu = 1;
    }
    if (lb) atomicOr(&f_bf16, 1);
    if (lf) atomicOr(&f_f32, 1);
    if (lu) atomicOr(&f_u8, 1);
    __syncthreads();
    if (threadIdx.x == 0)
        g_mask_mode = f_bf16 ? 3 : (f_f32 ? 1 : (f_u8 ? 0 : 2));
}

// ========== kernel 1a: split x into fp16 hi/lo ==========
__global__ void split_x_kernel(const float* __restrict__ x) {
    int i = blockIdx.x * blockDim.x + threadIdx.x;
    if (i >= B_ * IN_ / 4) return;
    float4 v = ((const float4*)x)[i];
    __half h[4], l[4];
    h[0] = __float2half_rn(v.x); l[0] = __float2half_rn(v.x - __half2float(h[0]));
    h[1] = __float2half_rn(v.y); l[1] = __float2half_rn(v.y - __half2float(h[1]));
    h[2] = __float2half_rn(v.z); l[2] = __float2half_rn(v.z - __half2float(h[2]));
    h[3] = __float2half_rn(v.w); l[3] = __float2half_rn(v.w - __half2float(h[3]));
    ((uint2*)g_xhi)[i] = *(uint2*)h;
    ((uint2*)g_xlo)[i] = *(uint2*)l;
}

// ========== kernel 1b: mask w1, store exact + fp16-hi only ==========
__global__ void split_w_kernel(const float* __restrict__ w1,
                               const void* __restrict__ mask) {
    int i = blockIdx.x * blockDim.x + threadIdx.x;
    if (i >= ND_ * IN_ / 4) return;
    int mode = g_mask_mode;
    float4 w = ((const float4*)w1)[i];
    bool m0, m1, m2, m3;
    if (mode == 0) {
        uchar4 mm = ((const uchar4*)mask)[i];
        m0 = mm.x; m1 = mm.y; m2 = mm.z; m3 = mm.w;
    } else if (mode == 1) {
        float4 mm = ((const float4*)mask)[i];
        m0 = mm.x != 0.f; m1 = mm.y != 0.f; m2 = mm.z != 0.f; m3 = mm.w != 0.f;
    } else if (mode == 2) {
        int4 mm = ((const int4*)mask)[i];
        m0 = mm.x != 0; m1 = mm.y != 0; m2 = mm.z != 0; m3 = mm.w != 0;
    } else {
        const __nv_bfloat16* mp = ((const __nv_bfloat16*)mask) + (size_t)i * 4;
        m0 = __bfloat162float(mp[0]) != 0.f; m1 = __bfloat162float(mp[1]) != 0.f;
        m2 = __bfloat162float(mp[2]) != 0.f; m3 = __bfloat162float(mp[3]) != 0.f;
    }
    w.x = m0 ? w.x : 0.f; w.y = m1 ? w.y : 0.f;
    w.z = m2 ? w.z : 0.f; w.w = m3 ? w.w : 0.f;
    ((float4*)g_w1m)[i] = w;
    __half h[4];
    h[0] = __float2half_rn(w.x);
    h[1] = __float2half_rn(w.y);
    h[2] = __float2half_rn(w.z);
    h[3] = __float2half_rn(w.w);
    ((uint2*)g_whi)[i] = *(uint2*)h;
}

// ========== kernel 2: wmma fp16 2-product GEMM, 2 CTAs/SM ==========
// h ~= (xhi + xlo) * whi.  CTA 128x128, K-chunk 32, 256 threads, warp tile 32x64.
#define GM_MT   128
#define GM_NT   128
#define GM_KC   32
#define NCHUNK  (IN_ / GM_KC)        // 32
#define ROWH    40                   // halfs per row (32 data + 8 pad)
#define ROWB    (ROWH * 2)           // 80 B

#define OFF_AHI 0
#define OFF_ALO (GM_MT * ROWB)                   // 10240
#define OFF_BHI (2 * GM_MT * ROWB)               // 20480
#define BUF_SZ  (2 * GM_MT * ROWB + GM_NT * ROWB)  // 30720
#define GEMM_SMEM (2 * BUF_SZ)                     // 61440

__device__ __forceinline__ void stage_chunk(uint32_t sbuf, int tid,
                                            int m0, int n0, int k0) {
    const __half* Xhi = g_xhi; const __half* Xlo = g_xlo;
    const __half* Whi = g_whi;
    // A: 128 rows x 4 x 16B = 512 slots (2 per thread), hi+lo
#pragma unroll
    for (int i = 0; i < 2; i++) {
        int v = tid + i * 256;
        int r = v >> 2, f = v & 3;
        uint32_t so = r * ROWB + f * 16;
        size_t g = (size_t)(m0 + r) * IN_ + k0 + f * 8;
        cp_async16(sbuf + OFF_AHI + so, &Xhi[g]);
        cp_async16(sbuf + OFF_ALO + so, &Xlo[g]);
    }
    // B: 128 rows x 4 x 16B = 512 slots (2 per thread), hi only
#pragma unroll
    for (int i = 0; i < 2; i++) {
        int v = tid + i * 256;
        int r = v >> 2, f = v & 3;
        uint32_t so = r * ROWB + f * 16;
        size_t g = (size_t)(n0 + r) * IN_ + k0 + f * 8;
        cp_async16(sbuf + OFF_BHI + so, &Whi[g]);
    }
}

__global__ void __launch_bounds__(256, 2)
gemm_fp16_kernel() {
    extern __shared__ char smem[];
    uint32_t sbase = smem_u32(smem);
    int tid = threadIdx.x;
    int wid = tid >> 5;
    int wm = wid & 3;          // 4 m-slices of 32
    int wn = wid >> 2;         // 2 n-slices of 64

    // swizzle: groups of (8 ntiles x 32 mtiles) = 256 CTAs -> L2 reuse
    int ing   = blockIdx.x & 255;
    int ntile = (blockIdx.x >> 8) * 8 + (ing & 7);
    int mtile = ing >> 3;
    int m0 = mtile * GM_MT;
    int n0 = ntile * GM_NT;

    wmma::fragment<wmma::accumulator, 16, 16, 16, float> acc[2][4];
#pragma unroll
    for (int i = 0; i < 2; i++)
#pragma unroll
        for (int j = 0; j < 4; j++) wmma::fill_fragment(acc[i][j], 0.f);

    stage_chunk(sbase, tid, m0, n0, 0);
    CP_COMMIT();

    for (int it = 0; it < NCHUNK; ++it) {
        if (it + 1 < NCHUNK) {
            stage_chunk(sbase + ((it + 1) & 1) * BUF_SZ, tid, m0, n0, (it + 1) * GM_KC);
            CP_COMMIT();
            CP_WAIT_1();
        } else {
            CP_WAIT_0();
        }
        __syncthreads();

        const __half* buf = (const __half*)(smem + (it & 1) * BUF_SZ);
        const __half* Ah = buf + (OFF_AHI / 2) + wm * 32 * ROWH;
        const __half* Al = buf + (OFF_ALO / 2) + wm * 32 * ROWH;
        const __half* Bh = buf + (OFF_BHI / 2) + wn * 64 * ROWH;

#pragma unroll
        for (int ks = 0; ks < 2; ks++) {
            wmma::fragment<wmma::matrix_a, 16, 16, 16, __half, wmma::row_major> ah[2], al[2];
#pragma unroll
            for (int mt = 0; mt < 2; mt++) {
                wmma::load_matrix_sync(ah[mt], Ah + mt * 16 * ROWH + ks * 16, ROWH);
                wmma::load_matrix_sync(al[mt], Al + mt * 16 * ROWH + ks * 16, ROWH);
            }
#pragma unroll
            for (int nt = 0; nt < 4; nt++) {
                wmma::fragment<wmma::matrix_b, 16, 16, 16, __half, wmma::col_major> bh;
                wmma::load_matrix_sync(bh, Bh + nt * 16 * ROWH + ks * 16, ROWH);
#pragma unroll
                for (int mt = 0; mt < 2; mt++) {
                    wmma::mma_sync(acc[mt][nt], ah[mt], bh, acc[mt][nt]);
                    wmma::mma_sync(acc[mt][nt], al[mt], bh, acc[mt][nt]);
                }
            }
        }
        __syncthreads();
    }

    float* base = g_h + (size_t)(m0 + wm * 32) * ND_ + n0 + wn * 64;
#pragma unroll
    for (int mt = 0; mt < 2; mt++)
#pragma unroll
        for (int nt = 0; nt < 4; nt++)
            wmma::store_matrix_sync(base + (size_t)mt * 16 * ND_ + nt * 16,
                                    acc[mt][nt], ND_, wmma::mem_row_major);
}

// ========== kernel 3: top-k + sequential-fp32 borderline fixup + output =====
__device__ __forceinline__ unsigned fkey(float f) {
    unsigned u = __float_as_uint(f);
    return (u & 0x80000000u) ? ~u : (u | 0x80000000u);
}
__device__ __forceinline__ float key2f(unsigned k) {
    unsigned u = (k & 0x80000000u) ? (k & 0x7FFFFFFFu) : ~k;
    return __uint_as_float(u);
}

#define BAND   8e-4f
#define SMAXN  64

__global__ void __launch_bounds__(256)
select_output_kernel(const float* __restrict__ H,
                     const float* __restrict__ x,
                     const float* __restrict__ b1,
                     const float* __restrict__ w2,
                     const float* __restrict__ b2,
                     float* __restrict__ out) {
    __shared__ float hs[ND_];            // 32 KB, h + bias
    __shared__ float xs[IN_];            // 4 KB, x row
    __shared__ unsigned int hist[256];
    __shared__ unsigned int s_prefix;
    __shared__ int s_kk;
    __shared__ int sN, sK1;
    __shared__ int   S_idx[SMAXN];
    __shared__ float S_val[SMAXN];
    __shared__ unsigned char S_win[SMAXN];

    int b = blockIdx.x;
    int t = threadIdx.x;

    // stage h + bias into smem; stage x row
    {
        const float4* hp = (const float4*)(H + (size_t)b * ND_);
        const float4* bp = (const float4*)b1;
        for (int i = t; i < ND_ / 4; i += 256) {
            float4 hv = hp[i];
            float4 bv = __ldg(bp + i);
            hv.x += bv.x; hv.y += bv.y; hv.z += bv.z; hv.w += bv.w;
            ((float4*)hs)[i] = hv;
        }
        const float4* xp = (const float4*)(x + (size_t)b * IN_);
        if (t < IN_ / 4) ((float4*)xs)[t] = __ldg(xp + t);
    }
    if (t == 0) { sN = 0; sK1 = 0; }
    __syncthreads();

    // ---- radix select: 4 passes, plain smem atomics (R1-proven) ----
    unsigned prefix = 0;
    int kk = KWIN_;
#pragma unroll 1
    for (int pass = 0; pass < 4; pass++) {
        int shift = 24 - pass * 8;
        hist[t] = 0;
        __syncthreads();
        for (int i = t; i < ND_; i += 256) {
            unsigned u = fkey(hs[i]);
            bool cand = (pass == 0) || ((u >> (shift + 8)) == (prefix >> (shift + 8)));
            if (cand) atomicAdd(&hist[(u >> shift) & 255u], 1u);
        }
        __syncthreads();
        if (t == 0) {
            unsigned cum = 0; int bin = 255;
            for (; bin > 0; bin--) {
                unsigned c = hist[bin];
                if (cum + c >= (unsigned)kk) break;
                cum += c;
            }
            s_prefix = prefix | ((unsigned)bin << shift);
            s_kk = kk - (int)cum;
        }
        __syncthreads();
        prefix = s_prefix;
        kk = s_kk;
        __syncthreads();
    }
    float thr_f = key2f(prefix);

    // ---- borderline detection (band = 6.5 sigma of 2-product GEMM noise) ----
    int cert = 0;
    for (int i = t; i < ND_; i += 256) {
        float vv = hs[i];
        if (vv > thr_f + BAND) cert++;
        else if (vv >= thr_f - BAND) {
            int s = atomicAdd(&sN, 1);
            if (s < SMAXN) S_idx[s] = i;
        }
    }
    if (cert) atomicAdd(&sK1, cert);
    __syncthreads();
    int nS = sN < SMAXN ? sN : SMAXN;

    // exact fp32 recompute, ONE THREAD per element, strictly ascending-k
    // sequential FMA chain (bit-correlated with the reference; zero flips R7/R9/R11/R13).
    for (int s = t; s < nS; s += 256) {
        int j = S_idx[s];
        const float4* wr = (const float4*)(g_w1m + (size_t)j * IN_);
        float a = 0.f;
#pragma unroll 8
        for (int q = 0; q < IN_ / 4; q++) {
            float4 xv = *(const float4*)&xs[q * 4];
            float4 wv = __ldg(wr + q);
            a = fmaf(xv.x, wv.x, a);
            a = fmaf(xv.y, wv.y, a);
            a = fmaf(xv.z, wv.z, a);
            a = fmaf(xv.w, wv.w, a);
        }
        S_val[s] = a + __ldg(&b1[j]);
    }
    __syncthreads();
    if (t == 0) {
        int need = KWIN_ - sK1;
        for (int s = 0; s < nS; s++) S_win[s] = 0;
        for (int r = 0; r < need && r < nS; r++) {
            int best = -1;
            for (int s = 0; s < nS; s++) {
                if (S_win[s]) continue;
                if (best < 0 || S_val[s] > S_val[best] ||
                    (S_val[s] == S_val[best] && S_idx[s] < S_idx[best])) best = s;
            }
            if (best >= 0) S_win[best] = 1;
        }
    }
    __syncthreads();

    // ---- block-diagonal contraction: 2 outputs per thread ----
    for (int o = t; o < OD_; o += 256) {
        const float* w2p = w2 + (size_t)o * (DPC_ * OD_) + o * DPC_;
        float w[16];
        *(float4*)&w[0]  = __ldg((const float4*)(w2p + 0));
        *(float4*)&w[4]  = __ldg((const float4*)(w2p + 4));
        *(float4*)&w[8]  = __ldg((const float4*)(w2p + 8));
        *(float4*)&w[12] = __ldg((const float4*)(w2p + 12));
        float s_out = __ldg(&b2[o]);
#pragma unroll
        for (int d = 0; d < DPC_; d++) {
            int j = o * DPC_ + d;
            float val = hs[j];
            bool win;
            if (val > thr_f + BAND) win = true;
            else if (val >= thr_f - BAND) {
                win = false;
                bool found = false;
                for (int s = 0; s < nS; s++) {
                    if (S_idx[s] == j) {
                        win = (S_win[s] != 0);
                        val = S_val[s];
                        found = true;
                        break;
                    }
                }
                if (!found) win = (fkey(val) >= prefix);  // list-overflow fallback
            } else win = false;
            if (win) s_out += val * w[d];
        }
        out[(size_t)b * OD_ + o] = s_out;
    }
}

// ========== launcher ==========
extern "C" void kernel_launch(void* const* d_in, const int* in_sizes, int n_in,
                              void* d_out, int out_size) {
    const float* x   = (const float*)d_in[0];
    const float* w1  = (const float*)d_in[1];
    const float* b1  = (const float*)d_in[2];
    const void*  msk = d_in[3];
    const float* w2  = (const float*)d_in[4];
    const float* b2  = (const float*)d_in[5];
    float* out = (float*)d_out;

    float* h_ptr; cudaGetSymbolAddress((void**)&h_ptr, g_h);

    cudaFuncSetAttribute(gemm_fp16_kernel,
                         cudaFuncAttributeMaxDynamicSharedMemorySize, GEMM_SMEM);

    probe_mask_kernel<<<1, 256>>>((const unsigned int*)msk);
    split_x_kernel<<<(B_ * IN_ / 4 + 255) / 256, 256>>>(x);
    split_w_kernel<<<(ND_ * IN_ / 4 + 255) / 256, 256>>>(w1, msk);
    gemm_fp16_kernel<<<(B_ / GM_MT) * (ND_ / GM_NT), 256, GEMM_SMEM>>>();
    select_output_kernel<<<B_, 256>>>(h_ptr, x, b1, w2, b2, out);
}

// round 15
// speedup vs baseline: 4.0264x; 1.1206x over previous
#include <cuda_runtime.h>
#include <cuda_bf16.h>
#include <cuda_fp16.h>
#include <mma.h>
#include <stdint.h>

using namespace nvcuda;

// Problem dims
#define B_     4096
#define IN_    1024
#define ND_    8192
#define OD_    512
#define DPC_   16
#define KWIN_  819

// ---------------- device scratch ----------------
__device__ __align__(16) __half g_xhi[(size_t)B_ * IN_];    // 8 MB
__device__ __align__(16) __half g_whi[(size_t)ND_ * IN_];   // 16 MB
__device__ __align__(16) float  g_w1m[(size_t)ND_ * IN_];   // 32 MB exact masked weights
__device__ __align__(16) float  g_h  [(size_t)B_ * ND_];    // 128 MB (no bias)
__device__ int   g_mask_mode;

__device__ __forceinline__ uint32_t smem_u32(const void* p) {
    uint32_t a;
    asm("{ .reg .u64 t; cvta.to.shared.u64 t, %1; cvt.u32.u64 %0, t; }" : "=r"(a) : "l"(p));
    return a;
}
__device__ __forceinline__ void cp_async16(uint32_t dst, const void* src) {
    asm volatile("cp.async.cg.shared.global [%0], [%1], 16;" :: "r"(dst), "l"(src));
}
#define CP_COMMIT()  asm volatile("cp.async.commit_group;" ::: "memory")
#define CP_WAIT_1()  asm volatile("cp.async.wait_group 1;" ::: "memory")
#define CP_WAIT_0()  asm volatile("cp.async.wait_group 0;" ::: "memory")

// ========== kernel 0: probe mask dtype (validated R1) ==========
__global__ void probe_mask_kernel(const unsigned int* __restrict__ m) {
    __shared__ int f_bf16, f_f32, f_u8;
    if (threadIdx.x == 0) { f_bf16 = 0; f_f32 = 0; f_u8 = 0; }
    __syncthreads();
    int lb = 0, lf = 0, lu = 0;
    for (int i = threadIdx.x; i < 4096; i += blockDim.x) {
        unsigned w = m[i];
        if (w == 0x00003F80u || w == 0x3F803F80u)   lb = 1;
        else if (w == 0x3F800000u)                  lf = 1;
        else if (w > 1u && (w & 0xFEFEFEFEu) == 0u) lu = 1;
    }
    if (lb) atomicOr(&f_bf16, 1);
    if (lf) atomicOr(&f_f32, 1);
    if (lu) atomicOr(&f_u8, 1);
    __syncthreads();
    if (threadIdx.x == 0)
        g_mask_mode = f_bf16 ? 3 : (f_f32 ? 1 : (f_u8 ? 0 : 2));
}

// ========== kernel 1a: x -> fp16 (hi only; lo dropped, fixup handles noise) ==
__global__ void split_x_kernel(const float* __restrict__ x) {
    int i = blockIdx.x * blockDim.x + threadIdx.x;
    if (i >= B_ * IN_ / 4) return;
    float4 v = ((const float4*)x)[i];
    __half h[4];
    h[0] = __float2half_rn(v.x);
    h[1] = __float2half_rn(v.y);
    h[2] = __float2half_rn(v.z);
    h[3] = __float2half_rn(v.w);
    ((uint2*)g_xhi)[i] = *(uint2*)h;
}

// ========== kernel 1b: mask w1, store exact + fp16-hi ==========
__global__ void split_w_kernel(const float* __restrict__ w1,
                               const void* __restrict__ mask) {
    int i = blockIdx.x * blockDim.x + threadIdx.x;
    if (i >= ND_ * IN_ / 4) return;
    int mode = g_mask_mode;
    float4 w = ((const float4*)w1)[i];
    bool m0, m1, m2, m3;
    if (mode == 0) {
        uchar4 mm = ((const uchar4*)mask)[i];
        m0 = mm.x; m1 = mm.y; m2 = mm.z; m3 = mm.w;
    } else if (mode == 1) {
        float4 mm = ((const float4*)mask)[i];
        m0 = mm.x != 0.f; m1 = mm.y != 0.f; m2 = mm.z != 0.f; m3 = mm.w != 0.f;
    } else if (mode == 2) {
        int4 mm = ((const int4*)mask)[i];
        m0 = mm.x != 0; m1 = mm.y != 0; m2 = mm.z != 0; m3 = mm.w != 0;
    } else {
        const __nv_bfloat16* mp = ((const __nv_bfloat16*)mask) + (size_t)i * 4;
        m0 = __bfloat162float(mp[0]) != 0.f; m1 = __bfloat162float(mp[1]) != 0.f;
        m2 = __bfloat162float(mp[2]) != 0.f; m3 = __bfloat162float(mp[3]) != 0.f;
    }
    w.x = m0 ? w.x : 0.f; w.y = m1 ? w.y : 0.f;
    w.z = m2 ? w.z : 0.f; w.w = m3 ? w.w : 0.f;
    ((float4*)g_w1m)[i] = w;
    __half h[4];
    h[0] = __float2half_rn(w.x);
    h[1] = __float2half_rn(w.y);
    h[2] = __float2half_rn(w.z);
    h[3] = __float2half_rn(w.w);
    ((uint2*)g_whi)[i] = *(uint2*)h;
}

// ========== kernel 2: wmma fp16 single-product GEMM, 2 CTAs/SM ==========
// h ~= xhi * whi.  CTA 128x128, K-chunk 32, 256 threads, warp tile 32x64.
#define GM_MT   128
#define GM_NT   128
#define GM_KC   32
#define NCHUNK  (IN_ / GM_KC)        // 32
#define ROWH    40                   // halfs per row (32 data + 8 pad)
#define ROWB    (ROWH * 2)           // 80 B

#define OFF_AHI 0
#define OFF_BHI (GM_MT * ROWB)               // 10240
#define BUF_SZ  (GM_MT * ROWB + GM_NT * ROWB)  // 20480
#define GEMM_SMEM (2 * BUF_SZ)                 // 40960

__device__ __forceinline__ void stage_chunk(uint32_t sbuf, int tid,
                                            int m0, int n0, int k0) {
    const __half* Xhi = g_xhi;
    const __half* Whi = g_whi;
    // A: 128 rows x 4 x 16B = 512 slots (2 per thread)
#pragma unroll
    for (int i = 0; i < 2; i++) {
        int v = tid + i * 256;
        int r = v >> 2, f = v & 3;
        uint32_t so = r * ROWB + f * 16;
        size_t g = (size_t)(m0 + r) * IN_ + k0 + f * 8;
        cp_async16(sbuf + OFF_AHI + so, &Xhi[g]);
    }
    // B: 128 rows x 4 x 16B = 512 slots (2 per thread)
#pragma unroll
    for (int i = 0; i < 2; i++) {
        int v = tid + i * 256;
        int r = v >> 2, f = v & 3;
        uint32_t so = r * ROWB + f * 16;
        size_t g = (size_t)(n0 + r) * IN_ + k0 + f * 8;
        cp_async16(sbuf + OFF_BHI + so, &Whi[g]);
    }
}

__global__ void __launch_bounds__(256, 2)
gemm_fp16_kernel() {
    extern __shared__ char smem[];
    uint32_t sbase = smem_u32(smem);
    int tid = threadIdx.x;
    int wid = tid >> 5;
    int wm = wid & 3;          // 4 m-slices of 32
    int wn = wid >> 2;         // 2 n-slices of 64

    // swizzle: groups of (8 ntiles x 32 mtiles) = 256 CTAs -> L2 reuse
    int ing   = blockIdx.x & 255;
    int ntile = (blockIdx.x >> 8) * 8 + (ing & 7);
    int mtile = ing >> 3;
    int m0 = mtile * GM_MT;
    int n0 = ntile * GM_NT;

    wmma::fragment<wmma::accumulator, 16, 16, 16, float> acc[2][4];
#pragma unroll
    for (int i = 0; i < 2; i++)
#pragma unroll
        for (int j = 0; j < 4; j++) wmma::fill_fragment(acc[i][j], 0.f);

    stage_chunk(sbase, tid, m0, n0, 0);
    CP_COMMIT();

    for (int it = 0; it < NCHUNK; ++it) {
        if (it + 1 < NCHUNK) {
            stage_chunk(sbase + ((it + 1) & 1) * BUF_SZ, tid, m0, n0, (it + 1) * GM_KC);
            CP_COMMIT();
            CP_WAIT_1();
        } else {
            CP_WAIT_0();
        }
        __syncthreads();

        const __half* buf = (const __half*)(smem + (it & 1) * BUF_SZ);
        const __half* Ah = buf + (OFF_AHI / 2) + wm * 32 * ROWH;
        const __half* Bh = buf + (OFF_BHI / 2) + wn * 64 * ROWH;

#pragma unroll
        for (int ks = 0; ks < 2; ks++) {
            wmma::fragment<wmma::matrix_a, 16, 16, 16, __half, wmma::row_major> ah[2];
#pragma unroll
            for (int mt = 0; mt < 2; mt++)
                wmma::load_matrix_sync(ah[mt], Ah + mt * 16 * ROWH + ks * 16, ROWH);
#pragma unroll
            for (int nt = 0; nt < 4; nt++) {
                wmma::fragment<wmma::matrix_b, 16, 16, 16, __half, wmma::col_major> bh;
                wmma::load_matrix_sync(bh, Bh + nt * 16 * ROWH + ks * 16, ROWH);
#pragma unroll
                for (int mt = 0; mt < 2; mt++)
                    wmma::mma_sync(acc[mt][nt], ah[mt], bh, acc[mt][nt]);
            }
        }
        __syncthreads();
    }

    float* base = g_h + (size_t)(m0 + wm * 32) * ND_ + n0 + wn * 64;
#pragma unroll
    for (int mt = 0; mt < 2; mt++)
#pragma unroll
        for (int nt = 0; nt < 4; nt++)
            wmma::store_matrix_sync(base + (size_t)mt * 16 * ND_ + nt * 16,
                                    acc[mt][nt], ND_, wmma::mem_row_major);
}

// ========== kernel 3: top-k + sequential-fp32 borderline fixup + output =====
__device__ __forceinline__ unsigned fkey(float f) {
    unsigned u = __float_as_uint(f);
    return (u & 0x80000000u) ? ~u : (u | 0x80000000u);
}
__device__ __forceinline__ float key2f(unsigned k) {
    unsigned u = (k & 0x80000000u) ? (k & 0x7FFFFFFFu) : ~k;
    return __uint_as_float(u);
}

#define BAND   8e-4f
#define SMAXN  64

__global__ void __launch_bounds__(256)
select_output_kernel(const float* __restrict__ H,
                     const float* __restrict__ x,
                     const float* __restrict__ b1,
                     const float* __restrict__ w2,
                     const float* __restrict__ b2,
                     float* __restrict__ out) {
    __shared__ float hs[ND_];            // 32 KB, h + bias
    __shared__ float xs[IN_];            // 4 KB, x row
    __shared__ unsigned int hist[256];
    __shared__ unsigned int s_prefix;
    __shared__ int s_kk;
    __shared__ int sN, sK1;
    __shared__ int   S_idx[SMAXN];
    __shared__ float S_val[SMAXN];
    __shared__ unsigned char S_win[SMAXN];

    int b = blockIdx.x;
    int t = threadIdx.x;
    int lane = t & 31;

    // stage h + bias into smem; stage x row
    {
        const float4* hp = (const float4*)(H + (size_t)b * ND_);
        const float4* bp = (const float4*)b1;
        for (int i = t; i < ND_ / 4; i += 256) {
            float4 hv = hp[i];
            float4 bv = __ldg(bp + i);
            hv.x += bv.x; hv.y += bv.y; hv.z += bv.z; hv.w += bv.w;
            ((float4*)hs)[i] = hv;
        }
        const float4* xp = (const float4*)(x + (size_t)b * IN_);
        if (t < IN_ / 4) ((float4*)xs)[t] = __ldg(xp + t);
    }
    if (t == 0) { sN = 0; sK1 = 0; }
    __syncthreads();

    // ---- radix select: 4 passes, warp-aggregated histogram atomics ----
    // (pass-0 keys concentrate into few exponent bins; match_any collapses a
    //  32-way same-bin conflict into ONE atomic with popc weight)
    unsigned prefix = 0;
    int kk = KWIN_;
#pragma unroll 1
    for (int pass = 0; pass < 4; pass++) {
        int shift = 24 - pass * 8;
        hist[t] = 0;
        __syncthreads();
        for (int i = t; i < ND_; i += 256) {   // uniform 32 iterations, no divergence
            unsigned u = fkey(hs[i]);
            bool cand = (pass == 0) || ((u >> (shift + 8)) == (prefix >> (shift + 8)));
            int bin = cand ? (int)((u >> shift) & 255u) : -1;
            unsigned mm = __match_any_sync(0xFFFFFFFFu, bin);
            if (bin >= 0 && (int)(__ffs(mm) - 1) == lane)
                atomicAdd(&hist[bin], (unsigned)__popc(mm));
        }
        __syncthreads();
        if (t == 0) {
            unsigned cum = 0; int bin = 255;
            for (; bin > 0; bin--) {
                unsigned c = hist[bin];
                if (cum + c >= (unsigned)kk) break;
                cum += c;
            }
            s_prefix = prefix | ((unsigned)bin << shift);
            s_kk = kk - (int)cum;
        }
        __syncthreads();
        prefix = s_prefix;
        kk = s_kk;
        __syncthreads();
    }
    float thr_f = key2f(prefix);

    // ---- borderline detection (band ~ 9 sigma of 1-product GEMM noise) ----
    int cert = 0;
    for (int i = t; i < ND_; i += 256) {
        float vv = hs[i];
        if (vv > thr_f + BAND) cert++;
        else if (vv >= thr_f - BAND) {
            int s = atomicAdd(&sN, 1);
            if (s < SMAXN) S_idx[s] = i;
        }
    }
    if (cert) atomicAdd(&sK1, cert);
    __syncthreads();
    int nS = sN < SMAXN ? sN : SMAXN;

    // exact fp32 recompute, ONE THREAD per element, strictly ascending-k
    // sequential FMA chain (bit-correlated with the reference; zero flips R7-R14).
    for (int s = t; s < nS; s += 256) {
        int j = S_idx[s];
        const float4* wr = (const float4*)(g_w1m + (size_t)j * IN_);
        float a = 0.f;
#pragma unroll 8
        for (int q = 0; q < IN_ / 4; q++) {
            float4 xv = *(const float4*)&xs[q * 4];
            float4 wv = __ldg(wr + q);
            a = fmaf(xv.x, wv.x, a);
            a = fmaf(xv.y, wv.y, a);
            a = fmaf(xv.z, wv.z, a);
            a = fmaf(xv.w, wv.w, a);
        }
        S_val[s] = a + __ldg(&b1[j]);
    }
    __syncthreads();
    if (t == 0) {
        int need = KWIN_ - sK1;
        for (int s = 0; s < nS; s++) S_win[s] = 0;
        for (int r = 0; r < need && r < nS; r++) {
            int best = -1;
            for (int s = 0; s < nS; s++) {
                if (S_win[s]) continue;
                if (best < 0 || S_val[s] > S_val[best] ||
                    (S_val[s] == S_val[best] && S_idx[s] < S_idx[best])) best = s;
            }
            if (best >= 0) S_win[best] = 1;
        }
    }
    __syncthreads();

    // ---- block-diagonal contraction: 2 outputs per thread ----
    for (int o = t; o < OD_; o += 256) {
        const float* w2p = w2 + (size_t)o * (DPC_ * OD_) + o * DPC_;
        float w[16];
        *(float4*)&w[0]  = __ldg((const float4*)(w2p + 0));
        *(float4*)&w[4]  = __ldg((const float4*)(w2p + 4));
        *(float4*)&w[8]  = __ldg((const float4*)(w2p + 8));
        *(float4*)&w[12] = __ldg((const float4*)(w2p + 12));
        float s_out = __ldg(&b2[o]);
#pragma unroll
        for (int d = 0; d < DPC_; d++) {
            int j = o * DPC_ + d;
            float val = hs[j];
            bool win;
            if (val > thr_f + BAND) win = true;
            else if (val >= thr_f - BAND) {
                win = false;
                bool found = false;
                for (int s = 0; s < nS; s++) {
                    if (S_idx[s] == j) {
                        win = (S_win[s] != 0);
                        val = S_val[s];
                        found = true;
                        break;
                    }
                }
                if (!found) win = (fkey(val) >= prefix);  // list-overflow fallback
            } else win = false;
            if (win) s_out += val * w[d];
        }
        out[(size_t)b * OD_ + o] = s_out;
    }
}

// ========== launcher ==========
extern "C" void kernel_launch(void* const* d_in, const int* in_sizes, int n_in,
                              void* d_out, int out_size) {
    const float* x   = (const float*)d_in[0];
    const float* w1  = (const float*)d_in[1];
    const float* b1  = (const float*)d_in[2];
    const void*  msk = d_in[3];
    const float* w2  = (const float*)d_in[4];
    const float* b2  = (const float*)d_in[5];
    float* out = (float*)d_out;

    float* h_ptr; cudaGetSymbolAddress((void**)&h_ptr, g_h);

    cudaFuncSetAttribute(gemm_fp16_kernel,
                         cudaFuncAttributeMaxDynamicSharedMemorySize, GEMM_SMEM);

    probe_mask_kernel<<<1, 256>>>((const unsigned int*)msk);
    split_x_kernel<<<(B_ * IN_ / 4 + 255) / 256, 256>>>(x);
    split_w_kernel<<<(ND_ * IN_ / 4 + 255) / 256, 256>>>(w1, msk);
    gemm_fp16_kernel<<<(B_ / GM_MT) * (ND_ / GM_NT), 256, GEMM_SMEM>>>();
    select_output_kernel<<<B_, 256>>>(h_ptr, x, b1, w2, b2, out);
}

// round 16
// speedup vs baseline: 5.3485x; 1.3284x over previous
#include <cuda_runtime.h>
#include <cuda_bf16.h>
#include <cuda_fp16.h>
#include <mma.h>
#include <stdint.h>

using namespace nvcuda;

// Problem dims
#define B_     4096
#define IN_    1024
#define ND_    8192
#define OD_    512
#define DPC_   16
#define KWIN_  819

// ---------------- device scratch ----------------
__device__ __align__(16) __half g_xhi[(size_t)B_ * IN_];    // 8 MB
__device__ __align__(16) __half g_whi[(size_t)ND_ * IN_];   // 16 MB
__device__ __align__(16) float  g_w1m[(size_t)ND_ * IN_];   // 32 MB exact masked weights
__device__ __align__(16) float  g_h  [(size_t)B_ * ND_];    // 128 MB (no bias)
__device__ int   g_mask_mode;

__device__ __forceinline__ uint32_t smem_u32(const void* p) {
    uint32_t a;
    asm("{ .reg .u64 t; cvta.to.shared.u64 t, %1; cvt.u32.u64 %0, t; }" : "=r"(a) : "l"(p));
    return a;
}
__device__ __forceinline__ void cp_async16(uint32_t dst, const void* src) {
    asm volatile("cp.async.cg.shared.global [%0], [%1], 16;" :: "r"(dst), "l"(src));
}
#define CP_COMMIT()  asm volatile("cp.async.commit_group;" ::: "memory")
#define CP_WAIT_1()  asm volatile("cp.async.wait_group 1;" ::: "memory")
#define CP_WAIT_0()  asm volatile("cp.async.wait_group 0;" ::: "memory")

// ========== kernel 0: probe mask dtype (validated R1) ==========
__global__ void probe_mask_kernel(const unsigned int* __restrict__ m) {
    __shared__ int f_bf16, f_f32, f_u8;
    if (threadIdx.x == 0) { f_bf16 = 0; f_f32 = 0; f_u8 = 0; }
    __syncthreads();
    int lb = 0, lf = 0, lu = 0;
    for (int i = threadIdx.x; i < 4096; i += blockDim.x) {
        unsigned w = m[i];
        if (w == 0x00003F80u || w == 0x3F803F80u)   lb = 1;
        else if (w == 0x3F800000u)                  lf = 1;
        else if (w > 1u && (w & 0xFEFEFEFEu) == 0u) lu = 1;
    }
    if (lb) atomicOr(&f_bf16, 1);
    if (lf) atomicOr(&f_f32, 1);
    if (lu) atomicOr(&f_u8, 1);
    __syncthreads();
    if (threadIdx.x == 0)
        g_mask_mode = f_bf16 ? 3 : (f_f32 ? 1 : (f_u8 ? 0 : 2));
}

// ========== kernel 1a: x -> fp16 ==========
__global__ void split_x_kernel(const float* __restrict__ x) {
    int i = blockIdx.x * blockDim.x + threadIdx.x;
    if (i >= B_ * IN_ / 4) return;
    float4 v = ((const float4*)x)[i];
    __half h[4];
    h[0] = __float2half_rn(v.x);
    h[1] = __float2half_rn(v.y);
    h[2] = __float2half_rn(v.z);
    h[3] = __float2half_rn(v.w);
    ((uint2*)g_xhi)[i] = *(uint2*)h;
}

// ========== kernel 1b: mask w1, store exact + fp16 ==========
__global__ void split_w_kernel(const float* __restrict__ w1,
                               const void* __restrict__ mask) {
    int i = blockIdx.x * blockDim.x + threadIdx.x;
    if (i >= ND_ * IN_ / 4) return;
    int mode = g_mask_mode;
    float4 w = ((const float4*)w1)[i];
    bool m0, m1, m2, m3;
    if (mode == 0) {
        uchar4 mm = ((const uchar4*)mask)[i];
        m0 = mm.x; m1 = mm.y; m2 = mm.z; m3 = mm.w;
    } else if (mode == 1) {
        float4 mm = ((const float4*)mask)[i];
        m0 = mm.x != 0.f; m1 = mm.y != 0.f; m2 = mm.z != 0.f; m3 = mm.w != 0.f;
    } else if (mode == 2) {
        int4 mm = ((const int4*)mask)[i];
        m0 = mm.x != 0; m1 = mm.y != 0; m2 = mm.z != 0; m3 = mm.w != 0;
    } else {
        const __nv_bfloat16* mp = ((const __nv_bfloat16*)mask) + (size_t)i * 4;
        m0 = __bfloat162float(mp[0]) != 0.f; m1 = __bfloat162float(mp[1]) != 0.f;
        m2 = __bfloat162float(mp[2]) != 0.f; m3 = __bfloat162float(mp[3]) != 0.f;
    }
    w.x = m0 ? w.x : 0.f; w.y = m1 ? w.y : 0.f;
    w.z = m2 ? w.z : 0.f; w.w = m3 ? w.w : 0.f;
    ((float4*)g_w1m)[i] = w;
    __half h[4];
    h[0] = __float2half_rn(w.x);
    h[1] = __float2half_rn(w.y);
    h[2] = __float2half_rn(w.z);
    h[3] = __float2half_rn(w.w);
    ((uint2*)g_whi)[i] = *(uint2*)h;
}

// ========== kernel 2: wmma fp16 single-product GEMM, 2 CTAs/SM (R15 WIN) =====
#define GM_MT   128
#define GM_NT   128
#define GM_KC   32
#define NCHUNK  (IN_ / GM_KC)        // 32
#define ROWH    40                   // halfs per row (32 data + 8 pad)
#define ROWB    (ROWH * 2)           // 80 B

#define OFF_AHI 0
#define OFF_BHI (GM_MT * ROWB)               // 10240
#define BUF_SZ  (GM_MT * ROWB + GM_NT * ROWB)  // 20480
#define GEMM_SMEM (2 * BUF_SZ)                 // 40960

__device__ __forceinline__ void stage_chunk(uint32_t sbuf, int tid,
                                            int m0, int n0, int k0) {
    const __half* Xhi = g_xhi;
    const __half* Whi = g_whi;
#pragma unroll
    for (int i = 0; i < 2; i++) {
        int v = tid + i * 256;
        int r = v >> 2, f = v & 3;
        uint32_t so = r * ROWB + f * 16;
        size_t g = (size_t)(m0 + r) * IN_ + k0 + f * 8;
        cp_async16(sbuf + OFF_AHI + so, &Xhi[g]);
    }
#pragma unroll
    for (int i = 0; i < 2; i++) {
        int v = tid + i * 256;
        int r = v >> 2, f = v & 3;
        uint32_t so = r * ROWB + f * 16;
        size_t g = (size_t)(n0 + r) * IN_ + k0 + f * 8;
        cp_async16(sbuf + OFF_BHI + so, &Whi[g]);
    }
}

__global__ void __launch_bounds__(256, 2)
gemm_fp16_kernel() {
    extern __shared__ char smem[];
    uint32_t sbase = smem_u32(smem);
    int tid = threadIdx.x;
    int wid = tid >> 5;
    int wm = wid & 3;
    int wn = wid >> 2;

    int ing   = blockIdx.x & 255;
    int ntile = (blockIdx.x >> 8) * 8 + (ing & 7);
    int mtile = ing >> 3;
    int m0 = mtile * GM_MT;
    int n0 = ntile * GM_NT;

    wmma::fragment<wmma::accumulator, 16, 16, 16, float> acc[2][4];
#pragma unroll
    for (int i = 0; i < 2; i++)
#pragma unroll
        for (int j = 0; j < 4; j++) wmma::fill_fragment(acc[i][j], 0.f);

    stage_chunk(sbase, tid, m0, n0, 0);
    CP_COMMIT();

    for (int it = 0; it < NCHUNK; ++it) {
        if (it + 1 < NCHUNK) {
            stage_chunk(sbase + ((it + 1) & 1) * BUF_SZ, tid, m0, n0, (it + 1) * GM_KC);
            CP_COMMIT();
            CP_WAIT_1();
        } else {
            CP_WAIT_0();
        }
        __syncthreads();

        const __half* buf = (const __half*)(smem + (it & 1) * BUF_SZ);
        const __half* Ah = buf + (OFF_AHI / 2) + wm * 32 * ROWH;
        const __half* Bh = buf + (OFF_BHI / 2) + wn * 64 * ROWH;

#pragma unroll
        for (int ks = 0; ks < 2; ks++) {
            wmma::fragment<wmma::matrix_a, 16, 16, 16, __half, wmma::row_major> ah[2];
#pragma unroll
            for (int mt = 0; mt < 2; mt++)
                wmma::load_matrix_sync(ah[mt], Ah + mt * 16 * ROWH + ks * 16, ROWH);
#pragma unroll
            for (int nt = 0; nt < 4; nt++) {
                wmma::fragment<wmma::matrix_b, 16, 16, 16, __half, wmma::col_major> bh;
                wmma::load_matrix_sync(bh, Bh + nt * 16 * ROWH + ks * 16, ROWH);
#pragma unroll
                for (int mt = 0; mt < 2; mt++)
                    wmma::mma_sync(acc[mt][nt], ah[mt], bh, acc[mt][nt]);
            }
        }
        __syncthreads();
    }

    float* base = g_h + (size_t)(m0 + wm * 32) * ND_ + n0 + wn * 64;
#pragma unroll
    for (int mt = 0; mt < 2; mt++)
#pragma unroll
        for (int nt = 0; nt < 4; nt++)
            wmma::store_matrix_sync(base + (size_t)mt * 16 * ND_ + nt * 16,
                                    acc[mt][nt], ND_, wmma::mem_row_major);
}

// ========== kernel 3: top-k + sequential-fp32 borderline fixup + output =====
__device__ __forceinline__ unsigned fkey(float f) {
    unsigned u = __float_as_uint(f);
    return (u & 0x80000000u) ? ~u : (u | 0x80000000u);
}
__device__ __forceinline__ float key2f(unsigned k) {
    unsigned u = (k & 0x80000000u) ? (k & 0x7FFFFFFFu) : ~k;
    return __uint_as_float(u);
}

#define BAND   8e-4f
#define SMAXN  64
#define NPASS  3   // 24-bit threshold: resolution ~9e-6 << BAND; 4th pass useless

__global__ void __launch_bounds__(256)
select_output_kernel(const float* __restrict__ H,
                     const float* __restrict__ x,
                     const float* __restrict__ b1,
                     const float* __restrict__ w2,
                     const float* __restrict__ b2,
                     float* __restrict__ out) {
    __shared__ float hs[ND_];            // 32 KB, h + bias
    __shared__ float xs[IN_];            // 4 KB, x row
    __shared__ unsigned int hist[256];
    __shared__ unsigned int s_prefix;
    __shared__ int s_kk;
    __shared__ int sN, sK1;
    __shared__ int   S_idx[SMAXN];
    __shared__ float S_val[SMAXN];
    __shared__ unsigned char S_win[SMAXN];

    int b = blockIdx.x;
    int t = threadIdx.x;

    // stage h + bias into smem; stage x row
    {
        const float4* hp = (const float4*)(H + (size_t)b * ND_);
        const float4* bp = (const float4*)b1;
        for (int i = t; i < ND_ / 4; i += 256) {
            float4 hv = hp[i];
            float4 bv = __ldg(bp + i);
            hv.x += bv.x; hv.y += bv.y; hv.z += bv.z; hv.w += bv.w;
            ((float4*)hs)[i] = hv;
        }
        const float4* xp = (const float4*)(x + (size_t)b * IN_);
        if (t < IN_ / 4) ((float4*)xs)[t] = __ldg(xp + t);
    }
    if (t == 0) { sN = 0; sK1 = 0; }
    __syncthreads();

    // ---- radix select: 3 passes, plain smem atomics + warp-parallel bin scan
    unsigned prefix = 0;
    int kk = KWIN_;
#pragma unroll 1
    for (int pass = 0; pass < NPASS; pass++) {
        int shift = 24 - pass * 8;
        hist[t] = 0;
        __syncthreads();
        for (int i = t; i < ND_; i += 256) {
            unsigned u = fkey(hs[i]);
            bool cand = (pass == 0) || ((u >> (shift + 8)) == (prefix >> (shift + 8)));
            if (cand) atomicAdd(&hist[(u >> shift) & 255u], 1u);
        }
        __syncthreads();
        // warp 0: lane L owns bins [8L, 8L+8); shfl suffix-scan across lanes,
        // serial 8-bin scan within the crossing lane. No extra block barriers.
        if (t < 32) {
            unsigned loc[8];
            unsigned lsum = 0;
#pragma unroll
            for (int j = 0; j < 8; j++) { loc[j] = hist[t * 8 + j]; lsum += loc[j]; }
            unsigned sfx = lsum;
#pragma unroll
            for (int d = 1; d < 32; d <<= 1) {
                unsigned o = __shfl_down_sync(0xFFFFFFFFu, sfx, d);
                if (t + d < 32) sfx += o;
            }
            unsigned above = sfx - lsum;            // sum over lanes > t
            if (above < (unsigned)kk && sfx >= (unsigned)kk) {   // crossing lane
                unsigned cum = above;
                int binsel = t * 8;
#pragma unroll 1
                for (int j = 7; j >= 0; j--) {
                    if (cum + loc[j] >= (unsigned)kk) { binsel = t * 8 + j; break; }
                    cum += loc[j];
                }
                s_prefix = prefix | ((unsigned)binsel << shift);
                s_kk = kk - (int)cum;
            }
        }
        __syncthreads();
        prefix = s_prefix;
        kk = s_kk;
        __syncthreads();
    }
    float thr_f = key2f(prefix);

    // ---- borderline detection (band ~ 9 sigma of GEMM noise) ----
    int cert = 0;
    for (int i = t; i < ND_; i += 256) {
        float vv = hs[i];
        if (vv > thr_f + BAND) cert++;
        else if (vv >= thr_f - BAND) {
            int s = atomicAdd(&sN, 1);
            if (s < SMAXN) S_idx[s] = i;
        }
    }
    if (cert) atomicAdd(&sK1, cert);
    __syncthreads();
    int nS = sN < SMAXN ? sN : SMAXN;

    // exact fp32 recompute, ONE THREAD per element, strictly ascending-k
    // sequential FMA chain (bit-correlated with the reference; zero flips R7-R15).
    for (int s = t; s < nS; s += 256) {
        int j = S_idx[s];
        const float4* wr = (const float4*)(g_w1m + (size_t)j * IN_);
        float a = 0.f;
#pragma unroll 16
        for (int q = 0; q < IN_ / 4; q++) {
            float4 xv = *(const float4*)&xs[q * 4];
            float4 wv = __ldg(wr + q);
            a = fmaf(xv.x, wv.x, a);
            a = fmaf(xv.y, wv.y, a);
            a = fmaf(xv.z, wv.z, a);
            a = fmaf(xv.w, wv.w, a);
        }
        S_val[s] = a + __ldg(&b1[j]);
    }
    __syncthreads();
    if (t == 0) {
        int need = KWIN_ - sK1;
        for (int s = 0; s < nS; s++) S_win[s] = 0;
        for (int r = 0; r < need && r < nS; r++) {
            int best = -1;
            for (int s = 0; s < nS; s++) {
                if (S_win[s]) continue;
                if (best < 0 || S_val[s] > S_val[best] ||
                    (S_val[s] == S_val[best] && S_idx[s] < S_idx[best])) best = s;
            }
            if (best >= 0) S_win[best] = 1;
        }
    }
    __syncthreads();

    // ---- block-diagonal contraction: 2 outputs per thread ----
    for (int o = t; o < OD_; o += 256) {
        const float* w2p = w2 + (size_t)o * (DPC_ * OD_) + o * DPC_;
        float w[16];
        *(float4*)&w[0]  = __ldg((const float4*)(w2p + 0));
        *(float4*)&w[4]  = __ldg((const float4*)(w2p + 4));
        *(float4*)&w[8]  = __ldg((const float4*)(w2p + 8));
        *(float4*)&w[12] = __ldg((const float4*)(w2p + 12));
        float s_out = __ldg(&b2[o]);
#pragma unroll
        for (int d = 0; d < DPC_; d++) {
            int j = o * DPC_ + d;
            float val = hs[j];
            bool win;
            if (val > thr_f + BAND) win = true;
            else if (val >= thr_f - BAND) {
                win = false;
                bool found = false;
                for (int s = 0; s < nS; s++) {
                    if (S_idx[s] == j) {
                        win = (S_win[s] != 0);
                        val = S_val[s];
                        found = true;
                        break;
                    }
                }
                if (!found) win = (fkey(val) >= prefix);  // list-overflow fallback
            } else win = false;
            if (win) s_out += val * w[d];
        }
        out[(size_t)b * OD_ + o] = s_out;
    }
}

// ========== launcher ==========
extern "C" void kernel_launch(void* const* d_in, const int* in_sizes, int n_in,
                              void* d_out, int out_size) {
    const float* x   = (const float*)d_in[0];
    const float* w1  = (const float*)d_in[1];
    const float* b1  = (const float*)d_in[2];
    const void*  msk = d_in[3];
    const float* w2  = (const float*)d_in[4];
    const float* b2  = (const float*)d_in[5];
    float* out = (float*)d_out;

    float* h_ptr; cudaGetSymbolAddress((void**)&h_ptr, g_h);

    cudaFuncSetAttribute(gemm_fp16_kernel,
                         cudaFuncAttributeMaxDynamicSharedMemorySize, GEMM_SMEM);

    probe_mask_kernel<<<1, 256>>>((const unsigned int*)msk);
    split_x_kernel<<<(B_ * IN_ / 4 + 255) / 256, 256>>>(x);
    split_w_kernel<<<(ND_ * IN_ / 4 + 255) / 256, 256>>>(w1, msk);
    gemm_fp16_kernel<<<(B_ / GM_MT) * (ND_ / GM_NT), 256, GEMM_SMEM>>>();
    select_output_kernel<<<B_, 256>>>(h_ptr, x, b1, w2, b2, out);
}